// round 7
// baseline (speedup 1.0000x reference)
#include <cuda_runtime.h>
#include <cuda_fp16.h>
#include <cstdint>
#include <math.h>

#define B_  2
#define N_  2048
#define D_  1024
#define H_  8
#define QH_ 16
#define DH_ 64
#define ROWS (B_*N_)   // 4096

// ---------------- scratch (device globals; no allocs) ----------------
__device__ __half g_xnh[(size_t)ROWS * D_];          // rmsnormed tokens (fp16)
__device__ float  g_qproj[(size_t)ROWS * 1024];      // x @ Wq
__device__ float  g_kv[(size_t)ROWS * 1024];         // x @ Wkv
__device__ __half g_qh[(size_t)B_ * QH_ * N_ * DH_]; // [b][qh][n][dh] fp16
__device__ __half g_kh[(size_t)B_ * H_  * N_ * DH_]; // [b][h][n][dh] fp16
__device__ __half g_vh[(size_t)B_ * H_  * N_ * DH_]; // [b][h][n][dh] fp16
__device__ __half g_och[(size_t)ROWS * (H_ * DH_)];  // attn out, group-summed (fp16)
__device__ __half g_Wqh [(size_t)1024 * 1024];       // fp16 Wq  [k][n]
__device__ __half g_Wkvh[(size_t)1024 * 1024];       // fp16 Wkv [k][n]
__device__ __half g_Woh [(size_t)512 * 1024];        // fp16 Wout[k][n]

// ---------------- helpers ----------------
__device__ __forceinline__ uint32_t smem_u32(const void* p) {
    uint32_t a;
    asm("{ .reg .u64 t; cvta.to.shared.u64 t, %1; cvt.u32.u64 %0, t; }" : "=r"(a) : "l"(p));
    return a;
}
__device__ __forceinline__ void cpa16(uint32_t dst, const void* src) {
    asm volatile("cp.async.ca.shared.global [%0], [%1], 16;" :: "r"(dst), "l"(src));
}
#define CP_COMMIT() asm volatile("cp.async.commit_group;" ::: "memory")
#define CP_WAIT(n)  asm volatile("cp.async.wait_group %0;" :: "n"(n) : "memory")

__device__ __forceinline__ void mmah(float* d, const uint32_t* a, const uint32_t* b) {
    asm volatile("mma.sync.aligned.m16n8k16.row.col.f32.f16.f16.f32 "
                 "{%0,%1,%2,%3}, {%4,%5,%6,%7}, {%8,%9}, {%0,%1,%2,%3};"
                 : "+f"(d[0]), "+f"(d[1]), "+f"(d[2]), "+f"(d[3])
                 : "r"(a[0]), "r"(a[1]), "r"(a[2]), "r"(a[3]),
                   "r"(b[0]), "r"(b[1]));
}
__device__ __forceinline__ void ldsm_x4(uint32_t* r, uint32_t addr) {
    asm volatile("ldmatrix.sync.aligned.m8n8.x4.shared.b16 {%0,%1,%2,%3}, [%4];"
                 : "=r"(r[0]), "=r"(r[1]), "=r"(r[2]), "=r"(r[3]) : "r"(addr));
}
__device__ __forceinline__ void ldsm_x2(uint32_t* r, uint32_t addr) {
    asm volatile("ldmatrix.sync.aligned.m8n8.x2.shared.b16 {%0,%1}, [%2];"
                 : "=r"(r[0]), "=r"(r[1]) : "r"(addr));
}
__device__ __forceinline__ void ldsm_x2t(uint32_t* r, uint32_t addr) {
    asm volatile("ldmatrix.sync.aligned.m8n8.x2.trans.shared.b16 {%0,%1}, [%2];"
                 : "=r"(r[0]), "=r"(r[1]) : "r"(addr));
}

// ---------------- 1) RMSNorm -> fp16 ----------------
__global__ __launch_bounds__(256) void k_rmsnorm(const float* __restrict__ x,
                                                 const float* __restrict__ w) {
    int row = blockIdx.x;
    const float4* xr = (const float4*)(x + (size_t)row * D_);
    float4 xv = xr[threadIdx.x];
    float ss = xv.x*xv.x + xv.y*xv.y + xv.z*xv.z + xv.w*xv.w;
    #pragma unroll
    for (int o = 16; o; o >>= 1) ss += __shfl_xor_sync(0xffffffffu, ss, o);
    __shared__ float sred[8];
    int wid = threadIdx.x >> 5, lid = threadIdx.x & 31;
    if (lid == 0) sred[wid] = ss;
    __syncthreads();
    if (wid == 0) {
        float v = (lid < 8) ? sred[lid] : 0.0f;
        #pragma unroll
        for (int o = 4; o; o >>= 1) v += __shfl_xor_sync(0xffffffffu, v, o);
        if (lid == 0) sred[0] = v;
    }
    __syncthreads();
    float s = rsqrtf(sred[0] * (1.0f / D_) + 1.192092896e-7f);
    float4 wv = ((const float4*)w)[threadIdx.x];
    __half2* dst = (__half2*)(g_xnh + (size_t)row * D_ + threadIdx.x * 4);
    dst[0] = __floats2half2_rn(xv.x * s * wv.x, xv.y * s * wv.y);
    dst[1] = __floats2half2_rn(xv.z * s * wv.z, xv.w * s * wv.w);
}

// ---------------- 2) fused f32 -> f16 weight convert ----------------
__global__ __launch_bounds__(256) void k_tohalf3(const float4* __restrict__ Wq,
                                                 const float4* __restrict__ Wkv,
                                                 const float4* __restrict__ Wo) {
    int i = blockIdx.x * 256 + threadIdx.x;   // < 655360
    const float4* src; __half2* dst; int j;
    if (i < 262144)      { src = Wq;  dst = (__half2*)g_Wqh;  j = i; }
    else if (i < 524288) { src = Wkv; dst = (__half2*)g_Wkvh; j = i - 262144; }
    else                 { src = Wo;  dst = (__half2*)g_Woh;  j = i - 524288; }
    float4 v = src[j];
    dst[2 * j]     = __floats2half2_rn(v.x, v.y);
    dst[2 * j + 1] = __floats2half2_rn(v.z, v.w);
}

// ---------------- 3) fp16 mma GEMM (proven in R5/R6) ----------------
#define HAS 40
#define HBS 136
#define HASZ (128 * HAS)
#define HBSZ (32 * HBS)
#define HSTG (HASZ + HBSZ)

__global__ __launch_bounds__(256) void k_gemmh(const __half* __restrict__ A,
                                               const __half* __restrict__ W,
                                               float* __restrict__ C, int K) {
    __shared__ __half hs[2 * HSTG];
    const int t = threadIdx.x, wid = t >> 5, lane = t & 31;
    const int wm = wid >> 2, wn = wid & 3;
    const int r = lane >> 2, cq = lane & 3;
    const int m0 = blockIdx.y * 128, n0 = blockIdx.x * 128;
    const uint32_t sb = smem_u32(hs);

    const int qa0 = t, qa1 = t + 256;
    const int ar0 = qa0 >> 2, ac0 = (qa0 & 3) * 8;
    const int ar1 = qa1 >> 2, ac1 = (qa1 & 3) * 8;
    const int br0 = qa0 >> 4, bc0 = (qa0 & 15) * 8;
    const int br1 = qa1 >> 4, bc1 = (qa1 & 15) * 8;

    const int lrow = lane & 7, lt = lane >> 3;
    const int aR = (lt & 1) * 8 + lrow;
    const int aC = (lt >> 1) * 8;
    const int lb = lane & 15, bt = lb >> 3, brw = lb & 7;

    float d[4][4][4];
    #pragma unroll
    for (int i = 0; i < 4; i++)
        #pragma unroll
        for (int j = 0; j < 4; j++)
            #pragma unroll
            for (int v = 0; v < 4; v++) d[i][j][v] = 0.0f;

    const int nc = K >> 5;

    #define LOAD_STAGE(s, c) do { \
        uint32_t ab = sb + (s) * (HSTG * 2); \
        uint32_t bb = ab + HASZ * 2; \
        int k0 = (c) << 5; \
        cpa16(ab + (ar0 * HAS + ac0) * 2, A + (size_t)(m0 + ar0) * K + k0 + ac0); \
        cpa16(ab + (ar1 * HAS + ac1) * 2, A + (size_t)(m0 + ar1) * K + k0 + ac1); \
        cpa16(bb + (br0 * HBS + bc0) * 2, W + (size_t)(k0 + br0) * 1024 + n0 + bc0); \
        cpa16(bb + (br1 * HBS + bc1) * 2, W + (size_t)(k0 + br1) * 1024 + n0 + bc1); \
        CP_COMMIT(); \
    } while (0)

    LOAD_STAGE(0, 0);

    for (int c = 0; c < nc; c++) {
        int s = c & 1;
        if (c + 1 < nc) { LOAD_STAGE(s ^ 1, c + 1); CP_WAIT(1); }
        else            { CP_WAIT(0); }
        __syncthreads();

        uint32_t ab = sb + s * (HSTG * 2);
        uint32_t bb = ab + HASZ * 2;
        #pragma unroll
        for (int ks = 0; ks < 2; ks++) {
            uint32_t a[4][4], b[4][2];
            #pragma unroll
            for (int mt = 0; mt < 4; mt++)
                ldsm_x4(a[mt], ab + ((wm * 64 + mt * 16 + aR) * HAS + ks * 16 + aC) * 2);
            #pragma unroll
            for (int nt = 0; nt < 4; nt++)
                ldsm_x2t(b[nt], bb + ((ks * 16 + bt * 8 + brw) * HBS + wn * 32 + nt * 8) * 2);
            #pragma unroll
            for (int mt = 0; mt < 4; mt++)
                #pragma unroll
                for (int nt = 0; nt < 4; nt++) mmah(d[mt][nt], a[mt], b[nt]);
        }
        __syncthreads();
    }

    #pragma unroll
    for (int mt = 0; mt < 4; mt++) {
        int row = m0 + wm * 64 + mt * 16 + r;
        #pragma unroll
        for (int nt = 0; nt < 4; nt++) {
            int col = n0 + wn * 32 + nt * 8 + 2 * cq;
            *(float2*)(C + (size_t)row * 1024 + col) = make_float2(d[mt][nt][0], d[mt][nt][1]);
            *(float2*)(C + (size_t)(row + 8) * 1024 + col) = make_float2(d[mt][nt][2], d[mt][nt][3]);
        }
    }
    #undef LOAD_STAGE
}

// ---------------- 4) fused q/k head norm + v copy -> fp16 ----------------
__global__ __launch_bounds__(256) void k_qknorm(const float* __restrict__ q_gamma,
                                                const float* __restrict__ k_gamma) {
    int warp = threadIdx.x >> 5, lane = threadIdx.x & 31;
    int vec = blockIdx.x * 8 + warp;          // < 98304
    if (vec < 65536) {
        // ---- q path ----
        int row = vec >> 4, qh = vec & 15;
        float2 x = *(const float2*)(g_qproj + (size_t)row * 1024 + qh * 64 + lane * 2);
        float ss = x.x * x.x + x.y * x.y;
        #pragma unroll
        for (int o = 16; o; o >>= 1) ss += __shfl_xor_sync(0xffffffffu, ss, o);
        float inv = 1.0f / fmaxf(sqrtf(ss), 1e-12f);
        float2 g = *(const float2*)(q_gamma + qh * 64 + lane * 2);
        int b = row >> 11, n = row & 2047;
        *(__half2*)(g_qh + ((((size_t)b * QH_ + qh) * N_ + n) * DH_) + lane * 2) =
            __floats2half2_rn(x.x * inv * (g.x + 1.0f) * 8.0f,
                              x.y * inv * (g.y + 1.0f) * 8.0f);
    } else {
        // ---- k/v path ----
        int v2 = vec - 65536;
        int row = v2 >> 3, h = v2 & 7;
        const float* base = g_kv + (size_t)row * 1024 + h * 64 + lane * 2;
        float2 kx = *(const float2*)base;
        float2 vx = *(const float2*)(base + 512);
        float ss = kx.x * kx.x + kx.y * kx.y;
        #pragma unroll
        for (int o = 16; o; o >>= 1) ss += __shfl_xor_sync(0xffffffffu, ss, o);
        float inv = 1.0f / fmaxf(sqrtf(ss), 1e-12f);
        float2 g = *(const float2*)(k_gamma + h * 64 + lane * 2);
        int b = row >> 11, n = row & 2047;
        size_t dst = (((size_t)b * H_ + h) * N_ + n) * DH_ + lane * 2;
        *(__half2*)(g_kh + dst) = __floats2half2_rn(kx.x * inv * (g.x + 1.0f) * 8.0f,
                                                    kx.y * inv * (g.y + 1.0f) * 8.0f);
        *(__half2*)(g_vh + dst) = __floats2half2_rn(vx.x, vx.y);
    }
}

// ---------------- 5) causal attention, 2 grouped heads / CTA ----------------
// smem halves (stride 72): Q[2][64] | K[2stg][64] | V[2stg][64] | P[2][64]
#define AQS 72
#define T46 4608
#define OFFK (2 * T46)
#define OFFV (4 * T46)
#define OFFP (6 * T46)
#define ATT2_SMEM (8 * T46 * 2)   // 73728 bytes

__global__ __launch_bounds__(256) void k_attn2() {
    extern __shared__ __half sh[];
    const uint32_t sb = smem_u32(sh);

    int bh = blockIdx.y;                        // b*8 + h
    int it = gridDim.x - 1 - blockIdx.x;        // biggest tiles first
    int b = bh >> 3, h = bh & 7;

    const __half* Qg0 = g_qh + (((size_t)(b * QH_ + 2 * h)) * N_ + it * 64) * DH_;
    const __half* Qg1 = Qg0 + (size_t)N_ * DH_;
    const __half* Kg = g_kh + ((size_t)bh) * N_ * DH_;
    const __half* Vg = g_vh + ((size_t)bh) * N_ * DH_;

    const int t = threadIdx.x, wid = t >> 5, lane = t & 31;
    const int wm = wid & 3, wn = wid >> 2;      // 4(m) x 2(n)
    const int r = lane >> 2, cq = lane & 3;
    const int row0 = wm * 16 + r;
    const int lrow = lane & 7, lt = lane >> 3;
    const int aR = (lt & 1) * 8 + lrow, aC = (lt >> 1) * 8;
    const int lb = lane & 15, bt = lb >> 3, brw = lb & 7;

    // load both Q tiles (sync, 2 uint4/thread/head)
    #pragma unroll
    for (int rep = 0; rep < 2; rep++) {
        int slot = rep * 256 + t;
        int i = slot >> 3, d8 = (slot & 7) * 8;
        *(uint4*)&sh[i * AQS + d8]       = *(const uint4*)(Qg0 + i * 64 + d8);
        *(uint4*)&sh[T46 + i * AQS + d8] = *(const uint4*)(Qg1 + i * 64 + d8);
    }

    #define LOADKV(s, jt_) do { \
        uint32_t kb_ = sb + (OFFK + (s) * T46) * 2; \
        uint32_t vb_ = sb + (OFFV + (s) * T46) * 2; \
        _Pragma("unroll") \
        for (int rep = 0; rep < 2; rep++) { \
            int slot = rep * 256 + t; \
            int j = slot >> 3, d8 = (slot & 7) * 8; \
            cpa16(kb_ + (j * AQS + d8) * 2, Kg + (size_t)((jt_) * 64 + j) * 64 + d8); \
            cpa16(vb_ + (j * AQS + d8) * 2, Vg + (size_t)((jt_) * 64 + j) * 64 + d8); \
        } \
        CP_COMMIT(); \
    } while (0)

    LOADKV(0, 0);

    float o[2][4][4];
    #pragma unroll
    for (int g = 0; g < 2; g++)
        #pragma unroll
        for (int nt = 0; nt < 4; nt++)
            #pragma unroll
            for (int v = 0; v < 4; v++) o[g][nt][v] = 0.0f;
    float srow[2] = {0.f, 0.f}, srow8[2] = {0.f, 0.f};

    for (int jt = 0; jt <= it; jt++) {
        int s = jt & 1;
        if (jt < it) { LOADKV(s ^ 1, jt + 1); CP_WAIT(1); }
        else         { CP_WAIT(0); }
        __syncthreads();

        uint32_t kb = sb + (OFFK + s * T46) * 2;
        uint32_t vb = sb + (OFFV + s * T46) * 2;

        // ---- S = Q K^T for both heads (K fragments shared) ----
        float dS[2][4][4];
        #pragma unroll
        for (int g = 0; g < 2; g++)
            #pragma unroll
            for (int nt = 0; nt < 4; nt++)
                #pragma unroll
                for (int v = 0; v < 4; v++) dS[g][nt][v] = 0.0f;

        #pragma unroll
        for (int ks = 0; ks < 4; ks++) {
            uint32_t a0[4], a1[4];
            uint32_t qoff = ((wm * 16 + aR) * AQS + ks * 16 + aC) * 2;
            ldsm_x4(a0, sb + qoff);
            ldsm_x4(a1, sb + T46 * 2 + qoff);
            #pragma unroll
            for (int nt = 0; nt < 4; nt++) {
                uint32_t bfr[2];
                ldsm_x2(bfr, kb + ((wn * 32 + nt * 8 + brw) * AQS + ks * 16 + bt * 8) * 2);
                mmah(dS[0][nt], a0, bfr);
                mmah(dS[1][nt], a1, bfr);
            }
        }

        // ---- softcap + exp + causal mask -> P (both heads) ----
        bool diag = (jt == it);
        int i0g = it * 64, j0g = jt * 64;
        #pragma unroll
        for (int g = 0; g < 2; g++) {
            __half* Ph = sh + OFFP + g * T46;
            #pragma unroll
            for (int nt = 0; nt < 4; nt++) {
                int colb = wn * 32 + nt * 8 + 2 * cq;
                float p[4];
                #pragma unroll
                for (int v = 0; v < 4; v++) {
                    int rr = i0g + row0 + ((v >= 2) ? 8 : 0);
                    int cc = j0g + colb + (v & 1);
                    float val = tanhf(dS[g][nt][v] * (1.0f / 50.0f)) * 6.25f;
                    p[v] = __expf(val);
                    if (diag && cc > rr) p[v] = 0.0f;
                }
                *(__half2*)&Ph[row0 * AQS + colb]       = __floats2half2_rn(p[0], p[1]);
                *(__half2*)&Ph[(row0 + 8) * AQS + colb] = __floats2half2_rn(p[2], p[3]);
            }
        }
        __syncthreads();

        // ---- O += P V for both heads (V fragments shared) ----
        #pragma unroll
        for (int c = 0; c < 4; c++) {
            uint32_t a0[4], a1[4];
            uint32_t poff = ((wm * 16 + aR) * AQS + c * 16 + aC) * 2;
            ldsm_x4(a0, sb + (OFFP) * 2 + poff);
            ldsm_x4(a1, sb + (OFFP + T46) * 2 + poff);
            {
                float2 f0 = __half22float2(*(__half2*)&a0[0]);
                float2 f2 = __half22float2(*(__half2*)&a0[2]);
                float2 f1 = __half22float2(*(__half2*)&a0[1]);
                float2 f3 = __half22float2(*(__half2*)&a0[3]);
                srow[0]  += f0.x + f0.y + f2.x + f2.y;
                srow8[0] += f1.x + f1.y + f3.x + f3.y;
                f0 = __half22float2(*(__half2*)&a1[0]);
                f2 = __half22float2(*(__half2*)&a1[2]);
                f1 = __half22float2(*(__half2*)&a1[1]);
                f3 = __half22float2(*(__half2*)&a1[3]);
                srow[1]  += f0.x + f0.y + f2.x + f2.y;
                srow8[1] += f1.x + f1.y + f3.x + f3.y;
            }
            #pragma unroll
            for (int nt = 0; nt < 4; nt++) {
                uint32_t bfr[2];
                ldsm_x2t(bfr, vb + ((c * 16 + bt * 8 + brw) * AQS + wn * 32 + nt * 8) * 2);
                mmah(o[0][nt], a0, bfr);
                mmah(o[1][nt], a1, bfr);
            }
        }
        __syncthreads();   // protect P/K/V before next iteration overwrites
    }

    // reduce row sums across cq lanes
    #pragma unroll
    for (int g = 0; g < 2; g++) {
        srow[g]  += __shfl_xor_sync(0xffffffffu, srow[g], 1);
        srow[g]  += __shfl_xor_sync(0xffffffffu, srow[g], 2);
        srow8[g] += __shfl_xor_sync(0xffffffffu, srow8[g], 1);
        srow8[g] += __shfl_xor_sync(0xffffffffu, srow8[g], 2);
    }
    float i0 = 1.0f / srow[0],  i1 = 1.0f / srow[1];
    float i08 = 1.0f / srow8[0], i18 = 1.0f / srow8[1];

    // write group-summed output directly (fp16)
    __half* Og = g_och + ((size_t)(b * N_) + it * 64) * 512 + h * 64;
    #pragma unroll
    for (int nt = 0; nt < 4; nt++) {
        int colb = wn * 32 + nt * 8 + 2 * cq;
        *(__half2*)(Og + (size_t)row0 * 512 + colb) =
            __floats2half2_rn(o[0][nt][0] * i0 + o[1][nt][0] * i1,
                              o[0][nt][1] * i0 + o[1][nt][1] * i1);
        *(__half2*)(Og + (size_t)(row0 + 8) * 512 + colb) =
            __floats2half2_rn(o[0][nt][2] * i08 + o[1][nt][2] * i18,
                              o[0][nt][3] * i08 + o[1][nt][3] * i18);
    }
    #undef LOADKV
}

// ---------------- launch ----------------
extern "C" void kernel_launch(void* const* d_in, const int* in_sizes, int n_in,
                              void* d_out, int out_size) {
    const float* tokens  = (const float*)d_in[0];
    const float* norm_w  = (const float*)d_in[1];
    const float* Wq      = (const float*)d_in[2];
    const float* Wkv     = (const float*)d_in[3];
    const float* Wout    = (const float*)d_in[4];
    const float* q_gamma = (const float*)d_in[5];
    const float* k_gamma = (const float*)d_in[6];
    float* out = (float*)d_out;

    static __half *Wqh_p = nullptr, *Wkvh_p = nullptr, *Woh_p = nullptr;
    static __half *xnh_p = nullptr, *och_p = nullptr;
    static float *qproj_p = nullptr, *kv_p = nullptr;
    if (!Wqh_p) {   // first call is the non-captured correctness run
        cudaGetSymbolAddress((void**)&Wqh_p, g_Wqh);
        cudaGetSymbolAddress((void**)&Wkvh_p, g_Wkvh);
        cudaGetSymbolAddress((void**)&Woh_p, g_Woh);
        cudaGetSymbolAddress((void**)&xnh_p, g_xnh);
        cudaGetSymbolAddress((void**)&och_p, g_och);
        cudaGetSymbolAddress((void**)&qproj_p, g_qproj);
        cudaGetSymbolAddress((void**)&kv_p, g_kv);
        cudaFuncSetAttribute(k_attn2, cudaFuncAttributeMaxDynamicSharedMemorySize, ATT2_SMEM);
    }

    k_rmsnorm<<<ROWS, 256>>>(tokens, norm_w);
    k_tohalf3<<<2560, 256>>>((const float4*)Wq, (const float4*)Wkv, (const float4*)Wout);
    k_gemmh<<<dim3(8, 32), 256>>>(xnh_p, Wqh_p,  qproj_p, 1024);
    k_gemmh<<<dim3(8, 32), 256>>>(xnh_p, Wkvh_p, kv_p,    1024);
    k_qknorm<<<12288, 256>>>(q_gamma, k_gamma);
    k_attn2<<<dim3(32, 16), 256, ATT2_SMEM>>>();
    k_gemmh<<<dim3(8, 32), 256>>>(och_p, Woh_p, out, 512);
}

// round 8
// speedup vs baseline: 1.1126x; 1.1126x over previous
#include <cuda_runtime.h>
#include <cuda_fp16.h>
#include <cstdint>
#include <math.h>

#define B_  2
#define N_  2048
#define D_  1024
#define H_  8
#define QH_ 16
#define DH_ 64
#define ROWS (B_*N_)   // 4096

// ---------------- scratch (device globals; no allocs) ----------------
__device__ __half g_xnh[(size_t)ROWS * D_];          // rmsnormed tokens (fp16)
__device__ float  g_qproj[(size_t)ROWS * 1024];      // x @ Wq
__device__ float  g_kv[(size_t)ROWS * 1024];         // x @ Wkv
__device__ __half g_qh[(size_t)B_ * QH_ * N_ * DH_]; // [b][qh][n][dh] fp16
__device__ __half g_kh[(size_t)B_ * H_  * N_ * DH_]; // [b][h][n][dh] fp16
__device__ __half g_vh[(size_t)B_ * H_  * N_ * DH_]; // [b][h][n][dh] fp16
__device__ __half g_och[(size_t)ROWS * (H_ * DH_)];  // attn out, group-summed (fp16)
__device__ __half g_Wqh [(size_t)1024 * 1024];       // fp16 Wq  [k][n]
__device__ __half g_Wkvh[(size_t)1024 * 1024];       // fp16 Wkv [k][n]
__device__ __half g_Woh [(size_t)512 * 1024];        // fp16 Wout[k][n]

// ---------------- helpers ----------------
__device__ __forceinline__ uint32_t smem_u32(const void* p) {
    uint32_t a;
    asm("{ .reg .u64 t; cvta.to.shared.u64 t, %1; cvt.u32.u64 %0, t; }" : "=r"(a) : "l"(p));
    return a;
}
__device__ __forceinline__ void cpa16(uint32_t dst, const void* src) {
    asm volatile("cp.async.ca.shared.global [%0], [%1], 16;" :: "r"(dst), "l"(src));
}
#define CP_COMMIT() asm volatile("cp.async.commit_group;" ::: "memory")
#define CP_WAIT(n)  asm volatile("cp.async.wait_group %0;" :: "n"(n) : "memory")

__device__ __forceinline__ void mmah(float* d, const uint32_t* a, const uint32_t* b) {
    asm volatile("mma.sync.aligned.m16n8k16.row.col.f32.f16.f16.f32 "
                 "{%0,%1,%2,%3}, {%4,%5,%6,%7}, {%8,%9}, {%0,%1,%2,%3};"
                 : "+f"(d[0]), "+f"(d[1]), "+f"(d[2]), "+f"(d[3])
                 : "r"(a[0]), "r"(a[1]), "r"(a[2]), "r"(a[3]),
                   "r"(b[0]), "r"(b[1]));
}
__device__ __forceinline__ void ldsm_x4(uint32_t* r, uint32_t addr) {
    asm volatile("ldmatrix.sync.aligned.m8n8.x4.shared.b16 {%0,%1,%2,%3}, [%4];"
                 : "=r"(r[0]), "=r"(r[1]), "=r"(r[2]), "=r"(r[3]) : "r"(addr));
}
__device__ __forceinline__ void ldsm_x2(uint32_t* r, uint32_t addr) {
    asm volatile("ldmatrix.sync.aligned.m8n8.x2.shared.b16 {%0,%1}, [%2];"
                 : "=r"(r[0]), "=r"(r[1]) : "r"(addr));
}
__device__ __forceinline__ void ldsm_x2t(uint32_t* r, uint32_t addr) {
    asm volatile("ldmatrix.sync.aligned.m8n8.x2.trans.shared.b16 {%0,%1}, [%2];"
                 : "=r"(r[0]), "=r"(r[1]) : "r"(addr));
}
// exp(6.25*tanh(s/50)) == exp(6.25 - 12.5/(1+e^{s/25})) ; exact fp32 path, ~5 instr
__device__ __forceinline__ float softcap_exp(float s) {
    float t = __expf(s * 0.04f);
    return __expf(6.25f - __fdividef(12.5f, 1.0f + t));
}

// ---------------- 1) RMSNorm -> fp16 ----------------
__global__ __launch_bounds__(256) void k_rmsnorm(const float* __restrict__ x,
                                                 const float* __restrict__ w) {
    int row = blockIdx.x;
    const float4* xr = (const float4*)(x + (size_t)row * D_);
    float4 xv = xr[threadIdx.x];
    float ss = xv.x*xv.x + xv.y*xv.y + xv.z*xv.z + xv.w*xv.w;
    #pragma unroll
    for (int o = 16; o; o >>= 1) ss += __shfl_xor_sync(0xffffffffu, ss, o);
    __shared__ float sred[8];
    int wid = threadIdx.x >> 5, lid = threadIdx.x & 31;
    if (lid == 0) sred[wid] = ss;
    __syncthreads();
    if (wid == 0) {
        float v = (lid < 8) ? sred[lid] : 0.0f;
        #pragma unroll
        for (int o = 4; o; o >>= 1) v += __shfl_xor_sync(0xffffffffu, v, o);
        if (lid == 0) sred[0] = v;
    }
    __syncthreads();
    float s = rsqrtf(sred[0] * (1.0f / D_) + 1.192092896e-7f);
    float4 wv = ((const float4*)w)[threadIdx.x];
    __half2* dst = (__half2*)(g_xnh + (size_t)row * D_ + threadIdx.x * 4);
    dst[0] = __floats2half2_rn(xv.x * s * wv.x, xv.y * s * wv.y);
    dst[1] = __floats2half2_rn(xv.z * s * wv.z, xv.w * s * wv.w);
}

// ---------------- 2) fused f32 -> f16 weight convert ----------------
__global__ __launch_bounds__(256) void k_tohalf3(const float4* __restrict__ Wq,
                                                 const float4* __restrict__ Wkv,
                                                 const float4* __restrict__ Wo) {
    int i = blockIdx.x * 256 + threadIdx.x;   // < 655360
    const float4* src; __half2* dst; int j;
    if (i < 262144)      { src = Wq;  dst = (__half2*)g_Wqh;  j = i; }
    else if (i < 524288) { src = Wkv; dst = (__half2*)g_Wkvh; j = i - 262144; }
    else                 { src = Wo;  dst = (__half2*)g_Woh;  j = i - 524288; }
    float4 v = src[j];
    dst[2 * j]     = __floats2half2_rn(v.x, v.y);
    dst[2 * j + 1] = __floats2half2_rn(v.z, v.w);
}

// ---------------- 3) fp16 mma GEMM core (2 W/C pairs fused: Q+KV) ----------------
#define HAS 40
#define HBS 136
#define HASZ (128 * HAS)
#define HBSZ (32 * HBS)
#define HSTG (HASZ + HBSZ)

template <int NX0>   // blocks in x for first output (8); NX0==gridDim.x -> single output
__global__ __launch_bounds__(256) void k_gemmh(const __half* __restrict__ A,
                                               const __half* __restrict__ W0,
                                               const __half* __restrict__ W1,
                                               float* __restrict__ C0,
                                               float* __restrict__ C1, int K) {
    __shared__ __half hs[2 * HSTG];
    const int t = threadIdx.x, wid = t >> 5, lane = t & 31;
    const int wm = wid >> 2, wn = wid & 3;
    const int r = lane >> 2, cq = lane & 3;
    const int m0 = blockIdx.y * 128;
    const __half* W; float* C; int n0;
    if ((int)blockIdx.x < NX0) { W = W0; C = C0; n0 = blockIdx.x * 128; }
    else                       { W = W1; C = C1; n0 = (blockIdx.x - NX0) * 128; }
    const uint32_t sb = smem_u32(hs);

    const int qa0 = t, qa1 = t + 256;
    const int ar0 = qa0 >> 2, ac0 = (qa0 & 3) * 8;
    const int ar1 = qa1 >> 2, ac1 = (qa1 & 3) * 8;
    const int br0 = qa0 >> 4, bc0 = (qa0 & 15) * 8;
    const int br1 = qa1 >> 4, bc1 = (qa1 & 15) * 8;

    const int lrow = lane & 7, lt = lane >> 3;
    const int aR = (lt & 1) * 8 + lrow;
    const int aC = (lt >> 1) * 8;
    const int lb = lane & 15, bt = lb >> 3, brw = lb & 7;

    float d[4][4][4];
    #pragma unroll
    for (int i = 0; i < 4; i++)
        #pragma unroll
        for (int j = 0; j < 4; j++)
            #pragma unroll
            for (int v = 0; v < 4; v++) d[i][j][v] = 0.0f;

    const int nc = K >> 5;

    #define LOAD_STAGE(s, c) do { \
        uint32_t ab = sb + (s) * (HSTG * 2); \
        uint32_t bb = ab + HASZ * 2; \
        int k0 = (c) << 5; \
        cpa16(ab + (ar0 * HAS + ac0) * 2, A + (size_t)(m0 + ar0) * K + k0 + ac0); \
        cpa16(ab + (ar1 * HAS + ac1) * 2, A + (size_t)(m0 + ar1) * K + k0 + ac1); \
        cpa16(bb + (br0 * HBS + bc0) * 2, W + (size_t)(k0 + br0) * 1024 + n0 + bc0); \
        cpa16(bb + (br1 * HBS + bc1) * 2, W + (size_t)(k0 + br1) * 1024 + n0 + bc1); \
        CP_COMMIT(); \
    } while (0)

    LOAD_STAGE(0, 0);

    for (int c = 0; c < nc; c++) {
        int s = c & 1;
        if (c + 1 < nc) { LOAD_STAGE(s ^ 1, c + 1); CP_WAIT(1); }
        else            { CP_WAIT(0); }
        __syncthreads();

        uint32_t ab = sb + s * (HSTG * 2);
        uint32_t bb = ab + HASZ * 2;
        #pragma unroll
        for (int ks = 0; ks < 2; ks++) {
            uint32_t a[4][4], b[4][2];
            #pragma unroll
            for (int mt = 0; mt < 4; mt++)
                ldsm_x4(a[mt], ab + ((wm * 64 + mt * 16 + aR) * HAS + ks * 16 + aC) * 2);
            #pragma unroll
            for (int nt = 0; nt < 4; nt++)
                ldsm_x2t(b[nt], bb + ((ks * 16 + bt * 8 + brw) * HBS + wn * 32 + nt * 8) * 2);
            #pragma unroll
            for (int mt = 0; mt < 4; mt++)
                #pragma unroll
                for (int nt = 0; nt < 4; nt++) mmah(d[mt][nt], a[mt], b[nt]);
        }
        __syncthreads();
    }

    #pragma unroll
    for (int mt = 0; mt < 4; mt++) {
        int row = m0 + wm * 64 + mt * 16 + r;
        #pragma unroll
        for (int nt = 0; nt < 4; nt++) {
            int col = n0 + wn * 32 + nt * 8 + 2 * cq;
            *(float2*)(C + (size_t)row * 1024 + col) = make_float2(d[mt][nt][0], d[mt][nt][1]);
            *(float2*)(C + (size_t)(row + 8) * 1024 + col) = make_float2(d[mt][nt][2], d[mt][nt][3]);
        }
    }
    #undef LOAD_STAGE
}

// ---------------- 4) fused q/k head norm + v copy -> fp16 ----------------
__global__ __launch_bounds__(256) void k_qknorm(const float* __restrict__ q_gamma,
                                                const float* __restrict__ k_gamma) {
    int warp = threadIdx.x >> 5, lane = threadIdx.x & 31;
    int vec = blockIdx.x * 8 + warp;          // < 98304
    if (vec < 65536) {
        int row = vec >> 4, qh = vec & 15;
        float2 x = *(const float2*)(g_qproj + (size_t)row * 1024 + qh * 64 + lane * 2);
        float ss = x.x * x.x + x.y * x.y;
        #pragma unroll
        for (int o = 16; o; o >>= 1) ss += __shfl_xor_sync(0xffffffffu, ss, o);
        float inv = 1.0f / fmaxf(sqrtf(ss), 1e-12f);
        float2 g = *(const float2*)(q_gamma + qh * 64 + lane * 2);
        int b = row >> 11, n = row & 2047;
        *(__half2*)(g_qh + ((((size_t)b * QH_ + qh) * N_ + n) * DH_) + lane * 2) =
            __floats2half2_rn(x.x * inv * (g.x + 1.0f) * 8.0f,
                              x.y * inv * (g.y + 1.0f) * 8.0f);
    } else {
        int v2 = vec - 65536;
        int row = v2 >> 3, h = v2 & 7;
        const float* base = g_kv + (size_t)row * 1024 + h * 64 + lane * 2;
        float2 kx = *(const float2*)base;
        float2 vx = *(const float2*)(base + 512);
        float ss = kx.x * kx.x + kx.y * kx.y;
        #pragma unroll
        for (int o = 16; o; o >>= 1) ss += __shfl_xor_sync(0xffffffffu, ss, o);
        float inv = 1.0f / fmaxf(sqrtf(ss), 1e-12f);
        float2 g = *(const float2*)(k_gamma + h * 64 + lane * 2);
        int b = row >> 11, n = row & 2047;
        size_t dst = (((size_t)b * H_ + h) * N_ + n) * DH_ + lane * 2;
        *(__half2*)(g_kh + dst) = __floats2half2_rn(kx.x * inv * (g.x + 1.0f) * 8.0f,
                                                    kx.y * inv * (g.y + 1.0f) * 8.0f);
        *(__half2*)(g_vh + dst) = __floats2half2_rn(vx.x, vx.y);
    }
}

// ---------------- 5) causal attention, 2 grouped heads / CTA ----------------
#define AQS 72
#define T46 4608
#define OFFK (2 * T46)
#define OFFV (4 * T46)
#define OFFP (6 * T46)
#define ATT2_SMEM (8 * T46 * 2)   // 73728 bytes

__global__ __launch_bounds__(256) void k_attn2() {
    extern __shared__ __half sh[];
    const uint32_t sb = smem_u32(sh);

    int bh = blockIdx.y;                        // b*8 + h
    int it = gridDim.x - 1 - blockIdx.x;        // biggest tiles first
    int b = bh >> 3, h = bh & 7;

    const __half* Qg0 = g_qh + (((size_t)(b * QH_ + 2 * h)) * N_ + it * 64) * DH_;
    const __half* Qg1 = Qg0 + (size_t)N_ * DH_;
    const __half* Kg = g_kh + ((size_t)bh) * N_ * DH_;
    const __half* Vg = g_vh + ((size_t)bh) * N_ * DH_;

    const int t = threadIdx.x, wid = t >> 5, lane = t & 31;
    const int wm = wid & 3, wn = wid >> 2;
    const int r = lane >> 2, cq = lane & 3;
    const int row0 = wm * 16 + r;
    const int lrow = lane & 7, lt = lane >> 3;
    const int aR = (lt & 1) * 8 + lrow, aC = (lt >> 1) * 8;
    const int lb = lane & 15, bt = lb >> 3, brw = lb & 7;

    #pragma unroll
    for (int rep = 0; rep < 2; rep++) {
        int slot = rep * 256 + t;
        int i = slot >> 3, d8 = (slot & 7) * 8;
        *(uint4*)&sh[i * AQS + d8]       = *(const uint4*)(Qg0 + i * 64 + d8);
        *(uint4*)&sh[T46 + i * AQS + d8] = *(const uint4*)(Qg1 + i * 64 + d8);
    }

    #define LOADKV(s, jt_) do { \
        uint32_t kb_ = sb + (OFFK + (s) * T46) * 2; \
        uint32_t vb_ = sb + (OFFV + (s) * T46) * 2; \
        _Pragma("unroll") \
        for (int rep = 0; rep < 2; rep++) { \
            int slot = rep * 256 + t; \
            int j = slot >> 3, d8 = (slot & 7) * 8; \
            cpa16(kb_ + (j * AQS + d8) * 2, Kg + (size_t)((jt_) * 64 + j) * 64 + d8); \
            cpa16(vb_ + (j * AQS + d8) * 2, Vg + (size_t)((jt_) * 64 + j) * 64 + d8); \
        } \
        CP_COMMIT(); \
    } while (0)

    LOADKV(0, 0);

    float o[2][4][4];
    #pragma unroll
    for (int g = 0; g < 2; g++)
        #pragma unroll
        for (int nt = 0; nt < 4; nt++)
            #pragma unroll
            for (int v = 0; v < 4; v++) o[g][nt][v] = 0.0f;
    float srow[2] = {0.f, 0.f}, srow8[2] = {0.f, 0.f};

    for (int jt = 0; jt <= it; jt++) {
        int s = jt & 1;
        if (jt < it) { LOADKV(s ^ 1, jt + 1); CP_WAIT(1); }
        else         { CP_WAIT(0); }
        __syncthreads();

        uint32_t kb = sb + (OFFK + s * T46) * 2;
        uint32_t vb = sb + (OFFV + s * T46) * 2;

        float dS[2][4][4];
        #pragma unroll
        for (int g = 0; g < 2; g++)
            #pragma unroll
            for (int nt = 0; nt < 4; nt++)
                #pragma unroll
                for (int v = 0; v < 4; v++) dS[g][nt][v] = 0.0f;

        #pragma unroll
        for (int ks = 0; ks < 4; ks++) {
            uint32_t a0[4], a1[4];
            uint32_t qoff = ((wm * 16 + aR) * AQS + ks * 16 + aC) * 2;
            ldsm_x4(a0, sb + qoff);
            ldsm_x4(a1, sb + T46 * 2 + qoff);
            #pragma unroll
            for (int nt = 0; nt < 4; nt++) {
                uint32_t bfr[2];
                ldsm_x2(bfr, kb + ((wn * 32 + nt * 8 + brw) * AQS + ks * 16 + bt * 8) * 2);
                mmah(dS[0][nt], a0, bfr);
                mmah(dS[1][nt], a1, bfr);
            }
        }

        // ---- fast exact softcap+exp; mask only on diagonal tiles ----
        if (jt == it) {
            #pragma unroll
            for (int g = 0; g < 2; g++) {
                __half* Ph = sh + OFFP + g * T46;
                #pragma unroll
                for (int nt = 0; nt < 4; nt++) {
                    int colb = wn * 32 + nt * 8 + 2 * cq;
                    float p0 = (colb     <= row0)     ? softcap_exp(dS[g][nt][0]) : 0.0f;
                    float p1 = (colb + 1 <= row0)     ? softcap_exp(dS[g][nt][1]) : 0.0f;
                    float p2 = (colb     <= row0 + 8) ? softcap_exp(dS[g][nt][2]) : 0.0f;
                    float p3 = (colb + 1 <= row0 + 8) ? softcap_exp(dS[g][nt][3]) : 0.0f;
                    *(__half2*)&Ph[row0 * AQS + colb]       = __floats2half2_rn(p0, p1);
                    *(__half2*)&Ph[(row0 + 8) * AQS + colb] = __floats2half2_rn(p2, p3);
                }
            }
        } else {
            #pragma unroll
            for (int g = 0; g < 2; g++) {
                __half* Ph = sh + OFFP + g * T46;
                #pragma unroll
                for (int nt = 0; nt < 4; nt++) {
                    int colb = wn * 32 + nt * 8 + 2 * cq;
                    *(__half2*)&Ph[row0 * AQS + colb] =
                        __floats2half2_rn(softcap_exp(dS[g][nt][0]), softcap_exp(dS[g][nt][1]));
                    *(__half2*)&Ph[(row0 + 8) * AQS + colb] =
                        __floats2half2_rn(softcap_exp(dS[g][nt][2]), softcap_exp(dS[g][nt][3]));
                }
            }
        }
        __syncthreads();

        #pragma unroll
        for (int c = 0; c < 4; c++) {
            uint32_t a0[4], a1[4];
            uint32_t poff = ((wm * 16 + aR) * AQS + c * 16 + aC) * 2;
            ldsm_x4(a0, sb + (OFFP) * 2 + poff);
            ldsm_x4(a1, sb + (OFFP + T46) * 2 + poff);
            {
                float2 f0 = __half22float2(*(__half2*)&a0[0]);
                float2 f2 = __half22float2(*(__half2*)&a0[2]);
                float2 f1 = __half22float2(*(__half2*)&a0[1]);
                float2 f3 = __half22float2(*(__half2*)&a0[3]);
                srow[0]  += f0.x + f0.y + f2.x + f2.y;
                srow8[0] += f1.x + f1.y + f3.x + f3.y;
                f0 = __half22float2(*(__half2*)&a1[0]);
                f2 = __half22float2(*(__half2*)&a1[2]);
                f1 = __half22float2(*(__half2*)&a1[1]);
                f3 = __half22float2(*(__half2*)&a1[3]);
                srow[1]  += f0.x + f0.y + f2.x + f2.y;
                srow8[1] += f1.x + f1.y + f3.x + f3.y;
            }
            #pragma unroll
            for (int nt = 0; nt < 4; nt++) {
                uint32_t bfr[2];
                ldsm_x2t(bfr, vb + ((c * 16 + bt * 8 + brw) * AQS + wn * 32 + nt * 8) * 2);
                mmah(o[0][nt], a0, bfr);
                mmah(o[1][nt], a1, bfr);
            }
        }
        __syncthreads();
    }

    #pragma unroll
    for (int g = 0; g < 2; g++) {
        srow[g]  += __shfl_xor_sync(0xffffffffu, srow[g], 1);
        srow[g]  += __shfl_xor_sync(0xffffffffu, srow[g], 2);
        srow8[g] += __shfl_xor_sync(0xffffffffu, srow8[g], 1);
        srow8[g] += __shfl_xor_sync(0xffffffffu, srow8[g], 2);
    }
    float i0 = 1.0f / srow[0],  i1 = 1.0f / srow[1];
    float i08 = 1.0f / srow8[0], i18 = 1.0f / srow8[1];

    __half* Og = g_och + ((size_t)(b * N_) + it * 64) * 512 + h * 64;
    #pragma unroll
    for (int nt = 0; nt < 4; nt++) {
        int colb = wn * 32 + nt * 8 + 2 * cq;
        *(__half2*)(Og + (size_t)row0 * 512 + colb) =
            __floats2half2_rn(o[0][nt][0] * i0 + o[1][nt][0] * i1,
                              o[0][nt][1] * i0 + o[1][nt][1] * i1);
        *(__half2*)(Og + (size_t)(row0 + 8) * 512 + colb) =
            __floats2half2_rn(o[0][nt][2] * i08 + o[1][nt][2] * i18,
                              o[0][nt][3] * i08 + o[1][nt][3] * i18);
    }
    #undef LOADKV
}

// ---------------- launch ----------------
extern "C" void kernel_launch(void* const* d_in, const int* in_sizes, int n_in,
                              void* d_out, int out_size) {
    const float* tokens  = (const float*)d_in[0];
    const float* norm_w  = (const float*)d_in[1];
    const float* Wq      = (const float*)d_in[2];
    const float* Wkv     = (const float*)d_in[3];
    const float* Wout    = (const float*)d_in[4];
    const float* q_gamma = (const float*)d_in[5];
    const float* k_gamma = (const float*)d_in[6];
    float* out = (float*)d_out;

    static __half *Wqh_p = nullptr, *Wkvh_p = nullptr, *Woh_p = nullptr;
    static __half *xnh_p = nullptr, *och_p = nullptr;
    static float *qproj_p = nullptr, *kv_p = nullptr;
    if (!Wqh_p) {   // first call is the non-captured correctness run
        cudaGetSymbolAddress((void**)&Wqh_p, g_Wqh);
        cudaGetSymbolAddress((void**)&Wkvh_p, g_Wkvh);
        cudaGetSymbolAddress((void**)&Woh_p, g_Woh);
        cudaGetSymbolAddress((void**)&xnh_p, g_xnh);
        cudaGetSymbolAddress((void**)&och_p, g_och);
        cudaGetSymbolAddress((void**)&qproj_p, g_qproj);
        cudaGetSymbolAddress((void**)&kv_p, g_kv);
        cudaFuncSetAttribute(k_attn2, cudaFuncAttributeMaxDynamicSharedMemorySize, ATT2_SMEM);
    }

    k_rmsnorm<<<ROWS, 256>>>(tokens, norm_w);
    k_tohalf3<<<2560, 256>>>((const float4*)Wq, (const float4*)Wkv, (const float4*)Wout);
    // fused Q+KV projection: 16 x-blocks (8 -> qproj, 8 -> kv)
    k_gemmh<8><<<dim3(16, 32), 256>>>(xnh_p, Wqh_p, Wkvh_p, qproj_p, kv_p, 1024);
    k_qknorm<<<12288, 256>>>(q_gamma, k_gamma);
    k_attn2<<<dim3(32, 16), 256, ATT2_SMEM>>>();
    // output projection (single output; NX0 = full grid)
    k_gemmh<8><<<dim3(8, 32), 256>>>(och_p, Woh_p, Woh_p, out, out, 512);
}

// round 10
// speedup vs baseline: 1.1682x; 1.0499x over previous
#include <cuda_runtime.h>
#include <cuda_fp16.h>
#include <cstdint>
#include <cstring>
#include <math.h>

#define B_  2
#define N_  2048
#define D_  1024
#define H_  8
#define QH_ 16
#define DH_ 64
#define ROWS (B_*N_)   // 4096

// ---------------- scratch (device globals; no allocs) ----------------
__device__ __half g_xnh[(size_t)ROWS * D_];           // rmsnormed tokens (fp16)
__device__ __half g_qprojh[(size_t)ROWS * 1024];      // x @ Wq (fp16)
__device__ __half g_kvh[(size_t)ROWS * 1024];         // x @ Wkv (fp16)
__device__ __half g_qh[(size_t)B_ * QH_ * N_ * DH_];  // [b][qh][n][dh] fp16
__device__ __half g_kh[(size_t)B_ * H_  * N_ * DH_];  // [b][h][n][dh] fp16
__device__ __half g_vh[(size_t)B_ * H_  * N_ * DH_];  // [b][h][n][dh] fp16
__device__ float  g_o[(size_t)B_ * QH_ * N_ * DH_];   // per-qhead attn out (fp32)
__device__ __half g_och[(size_t)ROWS * (H_ * DH_)];   // group-summed (fp16)
__device__ __half g_Wqh [(size_t)1024 * 1024];        // fp16 Wq  [k][n]
__device__ __half g_Wkvh[(size_t)1024 * 1024];        // fp16 Wkv [k][n]
__device__ __half g_Woh [(size_t)512 * 1024];         // fp16 Wout[k][n]

// ---------------- helpers ----------------
__device__ __forceinline__ uint32_t smem_u32(const void* p) {
    uint32_t a;
    asm("{ .reg .u64 t; cvta.to.shared.u64 t, %1; cvt.u32.u64 %0, t; }" : "=r"(a) : "l"(p));
    return a;
}
__device__ __forceinline__ uint32_t h2u(__half2 v) {
    uint32_t u;
    memcpy(&u, &v, 4);
    return u;
}
__device__ __forceinline__ void cpa16(uint32_t dst, const void* src) {
    asm volatile("cp.async.ca.shared.global [%0], [%1], 16;" :: "r"(dst), "l"(src));
}
#define CP_COMMIT() asm volatile("cp.async.commit_group;" ::: "memory")
#define CP_WAIT(n)  asm volatile("cp.async.wait_group %0;" :: "n"(n) : "memory")

__device__ __forceinline__ void mmah(float* d, const uint32_t* a, const uint32_t* b) {
    asm volatile("mma.sync.aligned.m16n8k16.row.col.f32.f16.f16.f32 "
                 "{%0,%1,%2,%3}, {%4,%5,%6,%7}, {%8,%9}, {%0,%1,%2,%3};"
                 : "+f"(d[0]), "+f"(d[1]), "+f"(d[2]), "+f"(d[3])
                 : "r"(a[0]), "r"(a[1]), "r"(a[2]), "r"(a[3]),
                   "r"(b[0]), "r"(b[1]));
}
__device__ __forceinline__ void ldsm_x4(uint32_t* r, uint32_t addr) {
    asm volatile("ldmatrix.sync.aligned.m8n8.x4.shared.b16 {%0,%1,%2,%3}, [%4];"
                 : "=r"(r[0]), "=r"(r[1]), "=r"(r[2]), "=r"(r[3]) : "r"(addr));
}
__device__ __forceinline__ void ldsm_x2(uint32_t* r, uint32_t addr) {
    asm volatile("ldmatrix.sync.aligned.m8n8.x2.shared.b16 {%0,%1}, [%2];"
                 : "=r"(r[0]), "=r"(r[1]) : "r"(addr));
}
__device__ __forceinline__ void ldsm_x2t(uint32_t* r, uint32_t addr) {
    asm volatile("ldmatrix.sync.aligned.m8n8.x2.trans.shared.b16 {%0,%1}, [%2];"
                 : "=r"(r[0]), "=r"(r[1]) : "r"(addr));
}
// exp(6.25*tanh(s/50)) == exp(6.25 - 12.5/(1+e^{s/25})) ; exact fp32 path
__device__ __forceinline__ float softcap_exp(float s) {
    float t = __expf(s * 0.04f);
    return __expf(6.25f - __fdividef(12.5f, 1.0f + t));
}
// epilogue store: fp32 or fp16
__device__ __forceinline__ void st2(float* C, size_t off, float x, float y) {
    *(float2*)(C + off) = make_float2(x, y);
}
__device__ __forceinline__ void st2(__half* C, size_t off, float x, float y) {
    *(__half2*)(C + off) = __floats2half2_rn(x, y);
}

// ---------------- 1) RMSNorm -> fp16 ----------------
__global__ __launch_bounds__(256) void k_rmsnorm(const float* __restrict__ x,
                                                 const float* __restrict__ w) {
    int row = blockIdx.x;
    const float4* xr = (const float4*)(x + (size_t)row * D_);
    float4 xv = xr[threadIdx.x];
    float ss = xv.x*xv.x + xv.y*xv.y + xv.z*xv.z + xv.w*xv.w;
    #pragma unroll
    for (int o = 16; o; o >>= 1) ss += __shfl_xor_sync(0xffffffffu, ss, o);
    __shared__ float sred[8];
    int wid = threadIdx.x >> 5, lid = threadIdx.x & 31;
    if (lid == 0) sred[wid] = ss;
    __syncthreads();
    if (wid == 0) {
        float v = (lid < 8) ? sred[lid] : 0.0f;
        #pragma unroll
        for (int o = 4; o; o >>= 1) v += __shfl_xor_sync(0xffffffffu, v, o);
        if (lid == 0) sred[0] = v;
    }
    __syncthreads();
    float s = rsqrtf(sred[0] * (1.0f / D_) + 1.192092896e-7f);
    float4 wv = ((const float4*)w)[threadIdx.x];
    __half2* dst = (__half2*)(g_xnh + (size_t)row * D_ + threadIdx.x * 4);
    dst[0] = __floats2half2_rn(xv.x * s * wv.x, xv.y * s * wv.y);
    dst[1] = __floats2half2_rn(xv.z * s * wv.z, xv.w * s * wv.w);
}

// ---------------- 2) fused f32 -> f16 weight convert ----------------
__global__ __launch_bounds__(256) void k_tohalf3(const float4* __restrict__ Wq,
                                                 const float4* __restrict__ Wkv,
                                                 const float4* __restrict__ Wo) {
    int i = blockIdx.x * 256 + threadIdx.x;   // < 655360
    const float4* src; __half2* dst; int j;
    if (i < 262144)      { src = Wq;  dst = (__half2*)g_Wqh;  j = i; }
    else if (i < 524288) { src = Wkv; dst = (__half2*)g_Wkvh; j = i - 262144; }
    else                 { src = Wo;  dst = (__half2*)g_Woh;  j = i - 524288; }
    float4 v = src[j];
    dst[2 * j]     = __floats2half2_rn(v.x, v.y);
    dst[2 * j + 1] = __floats2half2_rn(v.z, v.w);
}

// ---------------- 3) fp16 mma GEMM (output type templated) ----------------
#define HAS 40
#define HBS 136
#define HASZ (128 * HAS)
#define HBSZ (32 * HBS)
#define HSTG (HASZ + HBSZ)

template <int NX0, typename T>
__global__ __launch_bounds__(256) void k_gemmh(const __half* __restrict__ A,
                                               const __half* __restrict__ W0,
                                               const __half* __restrict__ W1,
                                               T* __restrict__ C0,
                                               T* __restrict__ C1, int K) {
    __shared__ __half hs[2 * HSTG];
    const int t = threadIdx.x, wid = t >> 5, lane = t & 31;
    const int wm = wid >> 2, wn = wid & 3;
    const int r = lane >> 2, cq = lane & 3;
    const int m0 = blockIdx.y * 128;
    const __half* W; T* C; int n0;
    if ((int)blockIdx.x < NX0) { W = W0; C = C0; n0 = blockIdx.x * 128; }
    else                       { W = W1; C = C1; n0 = (blockIdx.x - NX0) * 128; }
    const uint32_t sb = smem_u32(hs);

    const int qa0 = t, qa1 = t + 256;
    const int ar0 = qa0 >> 2, ac0 = (qa0 & 3) * 8;
    const int ar1 = qa1 >> 2, ac1 = (qa1 & 3) * 8;
    const int br0 = qa0 >> 4, bc0 = (qa0 & 15) * 8;
    const int br1 = qa1 >> 4, bc1 = (qa1 & 15) * 8;

    const int lrow = lane & 7, lt = lane >> 3;
    const int aR = (lt & 1) * 8 + lrow;
    const int aC = (lt >> 1) * 8;
    const int lb = lane & 15, bt = lb >> 3, brw = lb & 7;

    float d[4][4][4];
    #pragma unroll
    for (int i = 0; i < 4; i++)
        #pragma unroll
        for (int j = 0; j < 4; j++)
            #pragma unroll
            for (int v = 0; v < 4; v++) d[i][j][v] = 0.0f;

    const int nc = K >> 5;

    #define LOAD_STAGE(s, c) do { \
        uint32_t ab = sb + (s) * (HSTG * 2); \
        uint32_t bb = ab + HASZ * 2; \
        int k0 = (c) << 5; \
        cpa16(ab + (ar0 * HAS + ac0) * 2, A + (size_t)(m0 + ar0) * K + k0 + ac0); \
        cpa16(ab + (ar1 * HAS + ac1) * 2, A + (size_t)(m0 + ar1) * K + k0 + ac1); \
        cpa16(bb + (br0 * HBS + bc0) * 2, W + (size_t)(k0 + br0) * 1024 + n0 + bc0); \
        cpa16(bb + (br1 * HBS + bc1) * 2, W + (size_t)(k0 + br1) * 1024 + n0 + bc1); \
        CP_COMMIT(); \
    } while (0)

    LOAD_STAGE(0, 0);

    for (int c = 0; c < nc; c++) {
        int s = c & 1;
        if (c + 1 < nc) { LOAD_STAGE(s ^ 1, c + 1); CP_WAIT(1); }
        else            { CP_WAIT(0); }
        __syncthreads();

        uint32_t ab = sb + s * (HSTG * 2);
        uint32_t bb = ab + HASZ * 2;
        #pragma unroll
        for (int ks = 0; ks < 2; ks++) {
            uint32_t a[4][4], b[4][2];
            #pragma unroll
            for (int mt = 0; mt < 4; mt++)
                ldsm_x4(a[mt], ab + ((wm * 64 + mt * 16 + aR) * HAS + ks * 16 + aC) * 2);
            #pragma unroll
            for (int nt = 0; nt < 4; nt++)
                ldsm_x2t(b[nt], bb + ((ks * 16 + bt * 8 + brw) * HBS + wn * 32 + nt * 8) * 2);
            #pragma unroll
            for (int mt = 0; mt < 4; mt++)
                #pragma unroll
                for (int nt = 0; nt < 4; nt++) mmah(d[mt][nt], a[mt], b[nt]);
        }
        __syncthreads();
    }

    #pragma unroll
    for (int mt = 0; mt < 4; mt++) {
        int row = m0 + wm * 64 + mt * 16 + r;
        #pragma unroll
        for (int nt = 0; nt < 4; nt++) {
            int col = n0 + wn * 32 + nt * 8 + 2 * cq;
            st2(C, (size_t)row * 1024 + col, d[mt][nt][0], d[mt][nt][1]);
            st2(C, (size_t)(row + 8) * 1024 + col, d[mt][nt][2], d[mt][nt][3]);
        }
    }
    #undef LOAD_STAGE
}

// ---------------- 4) fused q/k head norm + v copy (fp16 in/out) ----------------
__global__ __launch_bounds__(256) void k_qknorm(const float* __restrict__ q_gamma,
                                                const float* __restrict__ k_gamma) {
    int warp = threadIdx.x >> 5, lane = threadIdx.x & 31;
    int vec = blockIdx.x * 8 + warp;          // < 98304
    if (vec < 65536) {
        int row = vec >> 4, qh = vec & 15;
        float2 x = __half22float2(
            *(const __half2*)(g_qprojh + (size_t)row * 1024 + qh * 64 + lane * 2));
        float ss = x.x * x.x + x.y * x.y;
        #pragma unroll
        for (int o = 16; o; o >>= 1) ss += __shfl_xor_sync(0xffffffffu, ss, o);
        float inv = 1.0f / fmaxf(sqrtf(ss), 1e-12f);
        float2 g = *(const float2*)(q_gamma + qh * 64 + lane * 2);
        int b = row >> 11, n = row & 2047;
        *(__half2*)(g_qh + ((((size_t)b * QH_ + qh) * N_ + n) * DH_) + lane * 2) =
            __floats2half2_rn(x.x * inv * (g.x + 1.0f) * 8.0f,
                              x.y * inv * (g.y + 1.0f) * 8.0f);
    } else {
        int v2 = vec - 65536;
        int row = v2 >> 3, h = v2 & 7;
        const __half* base = g_kvh + (size_t)row * 1024 + h * 64 + lane * 2;
        float2 kx = __half22float2(*(const __half2*)base);
        __half2 vx = *(const __half2*)(base + 512);
        float ss = kx.x * kx.x + kx.y * kx.y;
        #pragma unroll
        for (int o = 16; o; o >>= 1) ss += __shfl_xor_sync(0xffffffffu, ss, o);
        float inv = 1.0f / fmaxf(sqrtf(ss), 1e-12f);
        float2 g = *(const float2*)(k_gamma + h * 64 + lane * 2);
        int b = row >> 11, n = row & 2047;
        size_t dst = (((size_t)b * H_ + h) * N_ + n) * DH_ + lane * 2;
        *(__half2*)(g_kh + dst) = __floats2half2_rn(kx.x * inv * (g.x + 1.0f) * 8.0f,
                                                    kx.y * inv * (g.y + 1.0f) * 8.0f);
        *(__half2*)(g_vh + dst) = vx;
    }
}

// ---------------- 5) causal attention: P-in-register, 4 warps, 1 head/CTA ----------------
// smem halves (stride 72): Q[64] | K[2stg][64] | V[2stg][64]  = 5*4608 halves = 46080 B
#define AQS 72
#define T46 4608
#define OFFK T46
#define OFFV (3 * T46)
#define ATT3_SMEM (5 * T46 * 2)

__global__ __launch_bounds__(128) void k_attn3() {
    extern __shared__ __half sh[];
    const uint32_t sb = smem_u32(sh);

    int bqh = blockIdx.y;                       // b*16 + qh
    int it  = gridDim.x - 1 - blockIdx.x;       // biggest tiles first
    int b = bqh >> 4, qh = bqh & 15, h = qh >> 1;

    const __half* Qg = g_qh + (((size_t)bqh) * N_ + it * 64) * DH_;
    const __half* Kg = g_kh + ((size_t)(b * H_ + h)) * N_ * DH_;
    const __half* Vg = g_vh + ((size_t)(b * H_ + h)) * N_ * DH_;

    const int t = threadIdx.x, wm = t >> 5, lane = t & 31;
    const int r = lane >> 2, cq = lane & 3;
    const int row0 = wm * 16 + r;
    const int lrow = lane & 7, lt = lane >> 3;
    const int aR = (lt & 1) * 8 + lrow, aC = (lt >> 1) * 8;
    const int lb = lane & 15, bt = lb >> 3, brw = lb & 7;

    // Q tile: 64x64 fp16 (plain stores; first in-loop sync covers visibility)
    #pragma unroll
    for (int rep = 0; rep < 4; rep++) {
        int slot = rep * 128 + t;
        int i = slot >> 3, d8 = (slot & 7) * 8;
        *(uint4*)&sh[i * AQS + d8] = *(const uint4*)(Qg + i * 64 + d8);
    }

    #define LOADKV(s, jt_) do { \
        uint32_t kb_ = sb + (OFFK + (s) * T46) * 2; \
        uint32_t vb_ = sb + (OFFV + (s) * T46) * 2; \
        _Pragma("unroll") \
        for (int rep = 0; rep < 4; rep++) { \
            int slot = rep * 128 + t; \
            int j = slot >> 3, d8 = (slot & 7) * 8; \
            cpa16(kb_ + (j * AQS + d8) * 2, Kg + (size_t)((jt_) * 64 + j) * 64 + d8); \
            cpa16(vb_ + (j * AQS + d8) * 2, Vg + (size_t)((jt_) * 64 + j) * 64 + d8); \
        } \
        CP_COMMIT(); \
    } while (0)

    LOADKV(0, 0);

    float o[8][4];
    #pragma unroll
    for (int nt = 0; nt < 8; nt++)
        #pragma unroll
        for (int v = 0; v < 4; v++) o[nt][v] = 0.0f;
    float srow = 0.0f, srow8 = 0.0f;

    for (int jt = 0; jt <= it; jt++) {
        int s = jt & 1;
        CP_WAIT(0);            // buffer s complete (per-thread)
        __syncthreads();       // all threads' loads visible; prev reads of s^1 done
        if (jt < it) LOADKV(s ^ 1, jt + 1);   // overlap with compute below

        uint32_t kb = sb + (OFFK + s * T46) * 2;
        uint32_t vb = sb + (OFFV + s * T46) * 2;

        // ---- S = Q K^T : warp owns 16 rows x 64 keys ----
        float dS[8][4];
        #pragma unroll
        for (int nt = 0; nt < 8; nt++)
            #pragma unroll
            for (int v = 0; v < 4; v++) dS[nt][v] = 0.0f;

        #pragma unroll
        for (int ks = 0; ks < 4; ks++) {
            uint32_t a[4];
            ldsm_x4(a, sb + ((wm * 16 + aR) * AQS + ks * 16 + aC) * 2);
            #pragma unroll
            for (int nt = 0; nt < 8; nt++) {
                uint32_t bfr[2];
                ldsm_x2(bfr, kb + ((nt * 8 + brw) * AQS + ks * 16 + bt * 8) * 2);
                mmah(dS[nt], a, bfr);
            }
        }

        // ---- softcap+exp+mask -> pack P directly into PV A-fragments ----
        uint32_t ah[4][4];
        if (jt == it) {
            #pragma unroll
            for (int nt = 0; nt < 8; nt++) {
                int colb = nt * 8 + 2 * cq;
                float p0 = (colb     <= row0)     ? softcap_exp(dS[nt][0]) : 0.0f;
                float p1 = (colb + 1 <= row0)     ? softcap_exp(dS[nt][1]) : 0.0f;
                float p2 = (colb     <= row0 + 8) ? softcap_exp(dS[nt][2]) : 0.0f;
                float p3 = (colb + 1 <= row0 + 8) ? softcap_exp(dS[nt][3]) : 0.0f;
                srow  += p0 + p1;
                srow8 += p2 + p3;
                int c = nt >> 1, hi = (nt & 1) * 2;
                ah[c][hi]     = h2u(__floats2half2_rn(p0, p1));
                ah[c][hi + 1] = h2u(__floats2half2_rn(p2, p3));
            }
        } else {
            #pragma unroll
            for (int nt = 0; nt < 8; nt++) {
                float p0 = softcap_exp(dS[nt][0]);
                float p1 = softcap_exp(dS[nt][1]);
                float p2 = softcap_exp(dS[nt][2]);
                float p3 = softcap_exp(dS[nt][3]);
                srow  += p0 + p1;
                srow8 += p2 + p3;
                int c = nt >> 1, hi = (nt & 1) * 2;
                ah[c][hi]     = h2u(__floats2half2_rn(p0, p1));
                ah[c][hi + 1] = h2u(__floats2half2_rn(p2, p3));
            }
        }

        // ---- O += P V : 4 k-chunks x 8 dh-tiles ----
        #pragma unroll
        for (int c = 0; c < 4; c++) {
            #pragma unroll
            for (int nt = 0; nt < 8; nt++) {
                uint32_t bfr[2];
                ldsm_x2t(bfr, vb + ((c * 16 + bt * 8 + brw) * AQS + nt * 8) * 2);
                mmah(o[nt], ah[c], bfr);
            }
        }
    }

    srow  += __shfl_xor_sync(0xffffffffu, srow, 1);
    srow  += __shfl_xor_sync(0xffffffffu, srow, 2);
    srow8 += __shfl_xor_sync(0xffffffffu, srow8, 1);
    srow8 += __shfl_xor_sync(0xffffffffu, srow8, 2);
    float inv  = 1.0f / srow;
    float inv8 = 1.0f / srow8;

    float* Og = g_o + (((size_t)bqh) * N_ + it * 64) * DH_;
    #pragma unroll
    for (int nt = 0; nt < 8; nt++) {
        int colb = nt * 8 + 2 * cq;
        *(float2*)(Og + (size_t)row0 * 64 + colb) =
            make_float2(o[nt][0] * inv, o[nt][1] * inv);
        *(float2*)(Og + (size_t)(row0 + 8) * 64 + colb) =
            make_float2(o[nt][2] * inv8, o[nt][3] * inv8);
    }
    #undef LOADKV
}

// ---------------- 6) group-sum combine: och = o[2h] + o[2h+1] (fp16) ----------------
__global__ __launch_bounds__(256) void k_combine() {
    int s4 = blockIdx.x * 256 + threadIdx.x;   // float4 slot, < 524288
    int col = (s4 & 127) * 4;
    int row = s4 >> 7;
    int h = col >> 6, dh = col & 63;
    int b = row >> 11, n = row & 2047;
    const float* o1 = g_o + ((((size_t)b * QH_ + 2 * h) * N_ + n) * DH_ + dh);
    const float* o2 = o1 + (size_t)N_ * DH_;
    float4 a = *(const float4*)o1, c = *(const float4*)o2;
    __half2* dst = (__half2*)(g_och + (size_t)row * 512 + col);
    dst[0] = __floats2half2_rn(a.x + c.x, a.y + c.y);
    dst[1] = __floats2half2_rn(a.z + c.z, a.w + c.w);
}

// ---------------- launch ----------------
extern "C" void kernel_launch(void* const* d_in, const int* in_sizes, int n_in,
                              void* d_out, int out_size) {
    const float* tokens  = (const float*)d_in[0];
    const float* norm_w  = (const float*)d_in[1];
    const float* Wq      = (const float*)d_in[2];
    const float* Wkv     = (const float*)d_in[3];
    const float* Wout    = (const float*)d_in[4];
    const float* q_gamma = (const float*)d_in[5];
    const float* k_gamma = (const float*)d_in[6];
    float* out = (float*)d_out;

    static __half *Wqh_p = nullptr, *Wkvh_p = nullptr, *Woh_p = nullptr;
    static __half *xnh_p = nullptr, *och_p = nullptr, *qprojh_p = nullptr, *kvh_p = nullptr;
    if (!Wqh_p) {   // first call is the non-captured correctness run
        cudaGetSymbolAddress((void**)&Wqh_p, g_Wqh);
        cudaGetSymbolAddress((void**)&Wkvh_p, g_Wkvh);
        cudaGetSymbolAddress((void**)&Woh_p, g_Woh);
        cudaGetSymbolAddress((void**)&xnh_p, g_xnh);
        cudaGetSymbolAddress((void**)&och_p, g_och);
        cudaGetSymbolAddress((void**)&qprojh_p, g_qprojh);
        cudaGetSymbolAddress((void**)&kvh_p, g_kvh);
        cudaFuncSetAttribute(k_attn3, cudaFuncAttributeMaxDynamicSharedMemorySize, ATT3_SMEM);
    }

    k_rmsnorm<<<ROWS, 256>>>(tokens, norm_w);
    k_tohalf3<<<2560, 256>>>((const float4*)Wq, (const float4*)Wkv, (const float4*)Wout);
    k_gemmh<8, __half><<<dim3(16, 32), 256>>>(xnh_p, Wqh_p, Wkvh_p, qprojh_p, kvh_p, 1024);
    k_qknorm<<<12288, 256>>>(q_gamma, k_gamma);
    k_attn3<<<dim3(32, 32), 128, ATT3_SMEM>>>();
    k_combine<<<2048, 256>>>();
    k_gemmh<8, float><<<dim3(8, 32), 256>>>(och_p, Woh_p, Woh_p, out, out, 512);
}

// round 11
// speedup vs baseline: 1.1756x; 1.0063x over previous
#include <cuda_runtime.h>
#include <cuda_fp16.h>
#include <cstdint>
#include <cstring>
#include <math.h>

#define B_  2
#define N_  2048
#define D_  1024
#define H_  8
#define QH_ 16
#define DH_ 64
#define ROWS (B_*N_)   // 4096

// ---------------- scratch (device globals; no allocs) ----------------
__device__ __half g_xnh[(size_t)ROWS * D_];           // rmsnormed tokens (fp16)
__device__ __half g_qprojh[(size_t)ROWS * 1024];      // x @ Wq (fp16)
__device__ __half g_kvh[(size_t)ROWS * 1024];         // x @ Wkv (fp16)
__device__ __half g_qh[(size_t)B_ * QH_ * N_ * DH_];  // [b][qh][n][dh] fp16
__device__ __half g_kh[(size_t)B_ * H_  * N_ * DH_];  // [b][h][n][dh] fp16
__device__ __half g_vh[(size_t)B_ * H_  * N_ * DH_];  // [b][h][n][dh] fp16
__device__ __half g_oh[(size_t)B_ * QH_ * N_ * DH_];  // per-qhead attn out (fp16)
__device__ __half g_och[(size_t)ROWS * (H_ * DH_)];   // group-summed (fp16)
__device__ __half g_Wqh [(size_t)1024 * 1024];        // fp16 Wq  [k][n]
__device__ __half g_Wkvh[(size_t)1024 * 1024];        // fp16 Wkv [k][n]
__device__ __half g_Woh [(size_t)512 * 1024];         // fp16 Wout[k][n]

// ---------------- helpers ----------------
__device__ __forceinline__ uint32_t smem_u32(const void* p) {
    uint32_t a;
    asm("{ .reg .u64 t; cvta.to.shared.u64 t, %1; cvt.u32.u64 %0, t; }" : "=r"(a) : "l"(p));
    return a;
}
__device__ __forceinline__ uint32_t h2u(__half2 v) {
    uint32_t u;
    memcpy(&u, &v, 4);
    return u;
}
__device__ __forceinline__ void cpa16(uint32_t dst, const void* src) {
    asm volatile("cp.async.ca.shared.global [%0], [%1], 16;" :: "r"(dst), "l"(src));
}
#define CP_COMMIT() asm volatile("cp.async.commit_group;" ::: "memory")
#define CP_WAIT(n)  asm volatile("cp.async.wait_group %0;" :: "n"(n) : "memory")

__device__ __forceinline__ void mmah(float* d, const uint32_t* a, const uint32_t* b) {
    asm volatile("mma.sync.aligned.m16n8k16.row.col.f32.f16.f16.f32 "
                 "{%0,%1,%2,%3}, {%4,%5,%6,%7}, {%8,%9}, {%0,%1,%2,%3};"
                 : "+f"(d[0]), "+f"(d[1]), "+f"(d[2]), "+f"(d[3])
                 : "r"(a[0]), "r"(a[1]), "r"(a[2]), "r"(a[3]),
                   "r"(b[0]), "r"(b[1]));
}
__device__ __forceinline__ void ldsm_x4(uint32_t* r, uint32_t addr) {
    asm volatile("ldmatrix.sync.aligned.m8n8.x4.shared.b16 {%0,%1,%2,%3}, [%4];"
                 : "=r"(r[0]), "=r"(r[1]), "=r"(r[2]), "=r"(r[3]) : "r"(addr));
}
__device__ __forceinline__ void ldsm_x2(uint32_t* r, uint32_t addr) {
    asm volatile("ldmatrix.sync.aligned.m8n8.x2.shared.b16 {%0,%1}, [%2];"
                 : "=r"(r[0]), "=r"(r[1]) : "r"(addr));
}
__device__ __forceinline__ void ldsm_x2t(uint32_t* r, uint32_t addr) {
    asm volatile("ldmatrix.sync.aligned.m8n8.x2.trans.shared.b16 {%0,%1}, [%2];"
                 : "=r"(r[0]), "=r"(r[1]) : "r"(addr));
}
// P = exp(6.25 * tanh(s/50)); tanh via Pade[5/4] (err < 2e-5 for |x|<=1.5).
// MUFU cost: 1 rcp + 1 ex2 (was 2 ex2 + 1 rcp).
__device__ __forceinline__ float softcap_exp(float s) {
    float x  = s * 0.02f;
    float x2 = x * x;
    float num = x * fmaf(x2, fmaf(x2, 1.0f, 105.0f), 945.0f);
    float den = fmaf(x2, fmaf(x2, 15.0f, 420.0f), 945.0f);
    return __expf(6.25f * __fdividef(num, den));
}
// epilogue store: fp32 or fp16
__device__ __forceinline__ void st2(float* C, size_t off, float x, float y) {
    *(float2*)(C + off) = make_float2(x, y);
}
__device__ __forceinline__ void st2(__half* C, size_t off, float x, float y) {
    *(__half2*)(C + off) = __floats2half2_rn(x, y);
}

// ---------------- 1) fused RMSNorm->fp16 + weight fp32->fp16 ----------------
__global__ __launch_bounds__(256) void k_pre(const float* __restrict__ x,
                                             const float* __restrict__ w,
                                             const float4* __restrict__ Wq,
                                             const float4* __restrict__ Wkv,
                                             const float4* __restrict__ Wo) {
    if (blockIdx.x < 4096) {
        int row = blockIdx.x;
        const float4* xr = (const float4*)(x + (size_t)row * D_);
        float4 xv = xr[threadIdx.x];
        float ss = xv.x*xv.x + xv.y*xv.y + xv.z*xv.z + xv.w*xv.w;
        #pragma unroll
        for (int o = 16; o; o >>= 1) ss += __shfl_xor_sync(0xffffffffu, ss, o);
        __shared__ float sred[8];
        int wid = threadIdx.x >> 5, lid = threadIdx.x & 31;
        if (lid == 0) sred[wid] = ss;
        __syncthreads();
        if (wid == 0) {
            float v = (lid < 8) ? sred[lid] : 0.0f;
            #pragma unroll
            for (int o = 4; o; o >>= 1) v += __shfl_xor_sync(0xffffffffu, v, o);
            if (lid == 0) sred[0] = v;
        }
        __syncthreads();
        float s = rsqrtf(sred[0] * (1.0f / D_) + 1.192092896e-7f);
        float4 wv = ((const float4*)w)[threadIdx.x];
        __half2* dst = (__half2*)(g_xnh + (size_t)row * D_ + threadIdx.x * 4);
        dst[0] = __floats2half2_rn(xv.x * s * wv.x, xv.y * s * wv.y);
        dst[1] = __floats2half2_rn(xv.z * s * wv.z, xv.w * s * wv.w);
    } else {
        int i = (blockIdx.x - 4096) * 256 + threadIdx.x;   // < 655360
        const float4* src; __half2* dst; int j;
        if (i < 262144)      { src = Wq;  dst = (__half2*)g_Wqh;  j = i; }
        else if (i < 524288) { src = Wkv; dst = (__half2*)g_Wkvh; j = i - 262144; }
        else                 { src = Wo;  dst = (__half2*)g_Woh;  j = i - 524288; }
        float4 v = src[j];
        dst[2 * j]     = __floats2half2_rn(v.x, v.y);
        dst[2 * j + 1] = __floats2half2_rn(v.z, v.w);
    }
}

// ---------------- 2) fp16 mma GEMM, 3-stage cp.async pipeline ----------------
#define HAS 40
#define HBS 136
#define HASZ (128 * HAS)
#define HBSZ (32 * HBS)
#define HSTG (HASZ + HBSZ)          // 9472 halves / stage
#define GSM  (3 * HSTG * 2)         // 56832 bytes dynamic

template <int NX0, typename T>
__global__ __launch_bounds__(256) void k_gemmh(const __half* __restrict__ A,
                                               const __half* __restrict__ W0,
                                               const __half* __restrict__ W1,
                                               T* __restrict__ C0,
                                               T* __restrict__ C1, int K) {
    extern __shared__ __half hs[];
    const int t = threadIdx.x, wid = t >> 5, lane = t & 31;
    const int wm = wid >> 2, wn = wid & 3;
    const int r = lane >> 2, cq = lane & 3;
    const int m0 = blockIdx.y * 128;
    const __half* W; T* C; int n0;
    if ((int)blockIdx.x < NX0) { W = W0; C = C0; n0 = blockIdx.x * 128; }
    else                       { W = W1; C = C1; n0 = (blockIdx.x - NX0) * 128; }
    const uint32_t sb = smem_u32(hs);

    const int qa0 = t, qa1 = t + 256;
    const int ar0 = qa0 >> 2, ac0 = (qa0 & 3) * 8;
    const int ar1 = qa1 >> 2, ac1 = (qa1 & 3) * 8;
    const int br0 = qa0 >> 4, bc0 = (qa0 & 15) * 8;
    const int br1 = qa1 >> 4, bc1 = (qa1 & 15) * 8;

    const int lrow = lane & 7, lt = lane >> 3;
    const int aR = (lt & 1) * 8 + lrow;
    const int aC = (lt >> 1) * 8;
    const int lb = lane & 15, bt = lb >> 3, brw = lb & 7;

    float d[4][4][4];
    #pragma unroll
    for (int i = 0; i < 4; i++)
        #pragma unroll
        for (int j = 0; j < 4; j++)
            #pragma unroll
            for (int v = 0; v < 4; v++) d[i][j][v] = 0.0f;

    const int nc = K >> 5;

    #define LOAD_STAGE(s, c) do { \
        uint32_t ab = sb + (s) * (HSTG * 2); \
        uint32_t bb = ab + HASZ * 2; \
        int k0 = (c) << 5; \
        cpa16(ab + (ar0 * HAS + ac0) * 2, A + (size_t)(m0 + ar0) * K + k0 + ac0); \
        cpa16(ab + (ar1 * HAS + ac1) * 2, A + (size_t)(m0 + ar1) * K + k0 + ac1); \
        cpa16(bb + (br0 * HBS + bc0) * 2, W + (size_t)(k0 + br0) * 1024 + n0 + bc0); \
        cpa16(bb + (br1 * HBS + bc1) * 2, W + (size_t)(k0 + br1) * 1024 + n0 + bc1); \
        CP_COMMIT(); \
    } while (0)

    LOAD_STAGE(0, 0);
    LOAD_STAGE(1, 1);

    for (int c = 0; c < nc; c++) {
        if (c == nc - 1) { CP_WAIT(0); } else { CP_WAIT(1); }
        __syncthreads();   // stage c visible to all; all warps done with stage c-1
        if (c + 2 < nc) LOAD_STAGE((c + 2) % 3, c + 2);  // reuses buffer (c-1)%3

        uint32_t ab = sb + (c % 3) * (HSTG * 2);
        uint32_t bb = ab + HASZ * 2;
        #pragma unroll
        for (int ks = 0; ks < 2; ks++) {
            uint32_t a[4][4], b[4][2];
            #pragma unroll
            for (int mt = 0; mt < 4; mt++)
                ldsm_x4(a[mt], ab + ((wm * 64 + mt * 16 + aR) * HAS + ks * 16 + aC) * 2);
            #pragma unroll
            for (int nt = 0; nt < 4; nt++)
                ldsm_x2t(b[nt], bb + ((ks * 16 + bt * 8 + brw) * HBS + wn * 32 + nt * 8) * 2);
            #pragma unroll
            for (int mt = 0; mt < 4; mt++)
                #pragma unroll
                for (int nt = 0; nt < 4; nt++) mmah(d[mt][nt], a[mt], b[nt]);
        }
    }

    #pragma unroll
    for (int mt = 0; mt < 4; mt++) {
        int row = m0 + wm * 64 + mt * 16 + r;
        #pragma unroll
        for (int nt = 0; nt < 4; nt++) {
            int col = n0 + wn * 32 + nt * 8 + 2 * cq;
            st2(C, (size_t)row * 1024 + col, d[mt][nt][0], d[mt][nt][1]);
            st2(C, (size_t)(row + 8) * 1024 + col, d[mt][nt][2], d[mt][nt][3]);
        }
    }
    #undef LOAD_STAGE
}

// ---------------- 3) q/k head norm + v copy: uint4 lanes, 8-lane reduce ----------------
__global__ __launch_bounds__(256) void k_qknorm(const float* __restrict__ q_gamma,
                                                const float* __restrict__ k_gamma) {
    int warp = threadIdx.x >> 5, lane = threadIdx.x & 31;
    int sub = lane >> 3, e8 = (lane & 7) * 8;
    int vec = (blockIdx.x * 8 + warp) * 4 + sub;   // < 98304
    if (vec < 65536) {
        int row = vec >> 4, qh = vec & 15;
        uint4 raw = *(const uint4*)(g_qprojh + (size_t)row * 1024 + qh * 64 + e8);
        __half2 hv[4];
        memcpy(hv, &raw, 16);
        float2 f[4];
        float ss = 0.0f;
        #pragma unroll
        for (int j = 0; j < 4; j++) {
            f[j] = __half22float2(hv[j]);
            ss += f[j].x * f[j].x + f[j].y * f[j].y;
        }
        ss += __shfl_xor_sync(0xffffffffu, ss, 1);
        ss += __shfl_xor_sync(0xffffffffu, ss, 2);
        ss += __shfl_xor_sync(0xffffffffu, ss, 4);
        float inv = 1.0f / fmaxf(sqrtf(ss), 1e-12f);
        float4 g0 = *(const float4*)(q_gamma + qh * 64 + e8);
        float4 g1 = *(const float4*)(q_gamma + qh * 64 + e8 + 4);
        __half2 out[4];
        out[0] = __floats2half2_rn(f[0].x * inv * (g0.x + 1.0f) * 8.0f,
                                   f[0].y * inv * (g0.y + 1.0f) * 8.0f);
        out[1] = __floats2half2_rn(f[1].x * inv * (g0.z + 1.0f) * 8.0f,
                                   f[1].y * inv * (g0.w + 1.0f) * 8.0f);
        out[2] = __floats2half2_rn(f[2].x * inv * (g1.x + 1.0f) * 8.0f,
                                   f[2].y * inv * (g1.y + 1.0f) * 8.0f);
        out[3] = __floats2half2_rn(f[3].x * inv * (g1.z + 1.0f) * 8.0f,
                                   f[3].y * inv * (g1.w + 1.0f) * 8.0f);
        int b = row >> 11, n = row & 2047;
        uint4 packed;
        memcpy(&packed, out, 16);
        *(uint4*)(g_qh + ((((size_t)b * QH_ + qh) * N_ + n) * DH_) + e8) = packed;
    } else {
        int v2 = vec - 65536;
        int row = v2 >> 3, h = v2 & 7;
        const __half* base = g_kvh + (size_t)row * 1024 + h * 64 + e8;
        uint4 kraw = *(const uint4*)base;
        uint4 vraw = *(const uint4*)(base + 512);
        __half2 hv[4];
        memcpy(hv, &kraw, 16);
        float2 f[4];
        float ss = 0.0f;
        #pragma unroll
        for (int j = 0; j < 4; j++) {
            f[j] = __half22float2(hv[j]);
            ss += f[j].x * f[j].x + f[j].y * f[j].y;
        }
        ss += __shfl_xor_sync(0xffffffffu, ss, 1);
        ss += __shfl_xor_sync(0xffffffffu, ss, 2);
        ss += __shfl_xor_sync(0xffffffffu, ss, 4);
        float inv = 1.0f / fmaxf(sqrtf(ss), 1e-12f);
        float4 g0 = *(const float4*)(k_gamma + h * 64 + e8);
        float4 g1 = *(const float4*)(k_gamma + h * 64 + e8 + 4);
        __half2 out[4];
        out[0] = __floats2half2_rn(f[0].x * inv * (g0.x + 1.0f) * 8.0f,
                                   f[0].y * inv * (g0.y + 1.0f) * 8.0f);
        out[1] = __floats2half2_rn(f[1].x * inv * (g0.z + 1.0f) * 8.0f,
                                   f[1].y * inv * (g0.w + 1.0f) * 8.0f);
        out[2] = __floats2half2_rn(f[2].x * inv * (g1.x + 1.0f) * 8.0f,
                                   f[2].y * inv * (g1.y + 1.0f) * 8.0f);
        out[3] = __floats2half2_rn(f[3].x * inv * (g1.z + 1.0f) * 8.0f,
                                   f[3].y * inv * (g1.w + 1.0f) * 8.0f);
        int b = row >> 11, n = row & 2047;
        size_t dst = (((size_t)b * H_ + h) * N_ + n) * DH_ + e8;
        uint4 packed;
        memcpy(&packed, out, 16);
        *(uint4*)(g_kh + dst) = packed;
        *(uint4*)(g_vh + dst) = vraw;   // v: straight fp16 copy
    }
}

// ---------------- 4) causal attention: P-in-register, 4 warps, 1 head/CTA ----------------
// smem halves (stride 72): Q[64] | K[2stg][64] | V[2stg][64]  = 5*4608 halves = 46080 B
#define AQS 72
#define T46 4608
#define OFFK T46
#define OFFV (3 * T46)
#define ATT3_SMEM (5 * T46 * 2)

__global__ __launch_bounds__(128) void k_attn3() {
    extern __shared__ __half sh[];
    const uint32_t sb = smem_u32(sh);

    int bqh = blockIdx.y;                       // b*16 + qh
    int it  = gridDim.x - 1 - blockIdx.x;       // biggest tiles first
    int b = bqh >> 4, qh = bqh & 15, h = qh >> 1;

    const __half* Qg = g_qh + (((size_t)bqh) * N_ + it * 64) * DH_;
    const __half* Kg = g_kh + ((size_t)(b * H_ + h)) * N_ * DH_;
    const __half* Vg = g_vh + ((size_t)(b * H_ + h)) * N_ * DH_;

    const int t = threadIdx.x, wm = t >> 5, lane = t & 31;
    const int r = lane >> 2, cq = lane & 3;
    const int row0 = wm * 16 + r;
    const int lrow = lane & 7, lt = lane >> 3;
    const int aR = (lt & 1) * 8 + lrow, aC = (lt >> 1) * 8;
    const int lb = lane & 15, bt = lb >> 3, brw = lb & 7;

    #pragma unroll
    for (int rep = 0; rep < 4; rep++) {
        int slot = rep * 128 + t;
        int i = slot >> 3, d8 = (slot & 7) * 8;
        *(uint4*)&sh[i * AQS + d8] = *(const uint4*)(Qg + i * 64 + d8);
    }

    #define LOADKV(s, jt_) do { \
        uint32_t kb_ = sb + (OFFK + (s) * T46) * 2; \
        uint32_t vb_ = sb + (OFFV + (s) * T46) * 2; \
        _Pragma("unroll") \
        for (int rep = 0; rep < 4; rep++) { \
            int slot = rep * 128 + t; \
            int j = slot >> 3, d8 = (slot & 7) * 8; \
            cpa16(kb_ + (j * AQS + d8) * 2, Kg + (size_t)((jt_) * 64 + j) * 64 + d8); \
            cpa16(vb_ + (j * AQS + d8) * 2, Vg + (size_t)((jt_) * 64 + j) * 64 + d8); \
        } \
        CP_COMMIT(); \
    } while (0)

    LOADKV(0, 0);

    float o[8][4];
    #pragma unroll
    for (int nt = 0; nt < 8; nt++)
        #pragma unroll
        for (int v = 0; v < 4; v++) o[nt][v] = 0.0f;
    float srow = 0.0f, srow8 = 0.0f;

    for (int jt = 0; jt <= it; jt++) {
        int s = jt & 1;
        CP_WAIT(0);
        __syncthreads();
        if (jt < it) LOADKV(s ^ 1, jt + 1);

        uint32_t kb = sb + (OFFK + s * T46) * 2;
        uint32_t vb = sb + (OFFV + s * T46) * 2;

        float dS[8][4];
        #pragma unroll
        for (int nt = 0; nt < 8; nt++)
            #pragma unroll
            for (int v = 0; v < 4; v++) dS[nt][v] = 0.0f;

        #pragma unroll
        for (int ks = 0; ks < 4; ks++) {
            uint32_t a[4];
            ldsm_x4(a, sb + ((wm * 16 + aR) * AQS + ks * 16 + aC) * 2);
            #pragma unroll
            for (int nt = 0; nt < 8; nt++) {
                uint32_t bfr[2];
                ldsm_x2(bfr, kb + ((nt * 8 + brw) * AQS + ks * 16 + bt * 8) * 2);
                mmah(dS[nt], a, bfr);
            }
        }

        uint32_t ah[4][4];
        if (jt == it) {
            #pragma unroll
            for (int nt = 0; nt < 8; nt++) {
                int colb = nt * 8 + 2 * cq;
                float p0 = (colb     <= row0)     ? softcap_exp(dS[nt][0]) : 0.0f;
                float p1 = (colb + 1 <= row0)     ? softcap_exp(dS[nt][1]) : 0.0f;
                float p2 = (colb     <= row0 + 8) ? softcap_exp(dS[nt][2]) : 0.0f;
                float p3 = (colb + 1 <= row0 + 8) ? softcap_exp(dS[nt][3]) : 0.0f;
                srow  += p0 + p1;
                srow8 += p2 + p3;
                int c = nt >> 1, hi = (nt & 1) * 2;
                ah[c][hi]     = h2u(__floats2half2_rn(p0, p1));
                ah[c][hi + 1] = h2u(__floats2half2_rn(p2, p3));
            }
        } else {
            #pragma unroll
            for (int nt = 0; nt < 8; nt++) {
                float p0 = softcap_exp(dS[nt][0]);
                float p1 = softcap_exp(dS[nt][1]);
                float p2 = softcap_exp(dS[nt][2]);
                float p3 = softcap_exp(dS[nt][3]);
                srow  += p0 + p1;
                srow8 += p2 + p3;
                int c = nt >> 1, hi = (nt & 1) * 2;
                ah[c][hi]     = h2u(__floats2half2_rn(p0, p1));
                ah[c][hi + 1] = h2u(__floats2half2_rn(p2, p3));
            }
        }

        #pragma unroll
        for (int c = 0; c < 4; c++) {
            #pragma unroll
            for (int nt = 0; nt < 8; nt++) {
                uint32_t bfr[2];
                ldsm_x2t(bfr, vb + ((c * 16 + bt * 8 + brw) * AQS + nt * 8) * 2);
                mmah(o[nt], ah[c], bfr);
            }
        }
    }

    srow  += __shfl_xor_sync(0xffffffffu, srow, 1);
    srow  += __shfl_xor_sync(0xffffffffu, srow, 2);
    srow8 += __shfl_xor_sync(0xffffffffu, srow8, 1);
    srow8 += __shfl_xor_sync(0xffffffffu, srow8, 2);
    float inv  = 1.0f / srow;
    float inv8 = 1.0f / srow8;

    __half* Og = g_oh + (((size_t)bqh) * N_ + it * 64) * DH_;
    #pragma unroll
    for (int nt = 0; nt < 8; nt++) {
        int colb = nt * 8 + 2 * cq;
        *(__half2*)(Og + (size_t)row0 * 64 + colb) =
            __floats2half2_rn(o[nt][0] * inv, o[nt][1] * inv);
        *(__half2*)(Og + (size_t)(row0 + 8) * 64 + colb) =
            __floats2half2_rn(o[nt][2] * inv8, o[nt][3] * inv8);
    }
    #undef LOADKV
}

// ---------------- 5) group-sum combine (fp16 in/out, 8 halves/thread) ----------------
__global__ __launch_bounds__(256) void k_combine() {
    int s8 = blockIdx.x * 256 + threadIdx.x;   // 8-half slot, < 262144
    int col = (s8 & 63) * 8;                   // 0..511 step 8
    int row = s8 >> 6;                         // b*N + n
    int h = col >> 6, dh = col & 63;
    int b = row >> 11, n = row & 2047;
    const __half* o1 = g_oh + ((((size_t)b * QH_ + 2 * h) * N_ + n) * DH_ + dh);
    const __half* o2 = o1 + (size_t)N_ * DH_;
    uint4 araw = *(const uint4*)o1, craw = *(const uint4*)o2;
    __half2 a[4], c[4], y[4];
    memcpy(a, &araw, 16);
    memcpy(c, &craw, 16);
    #pragma unroll
    for (int j = 0; j < 4; j++) {
        float2 fa = __half22float2(a[j]), fc = __half22float2(c[j]);
        y[j] = __floats2half2_rn(fa.x + fc.x, fa.y + fc.y);
    }
    uint4 packed;
    memcpy(&packed, y, 16);
    *(uint4*)(g_och + (size_t)row * 512 + col) = packed;
}

// ---------------- launch ----------------
extern "C" void kernel_launch(void* const* d_in, const int* in_sizes, int n_in,
                              void* d_out, int out_size) {
    const float* tokens  = (const float*)d_in[0];
    const float* norm_w  = (const float*)d_in[1];
    const float* Wq      = (const float*)d_in[2];
    const float* Wkv     = (const float*)d_in[3];
    const float* Wout    = (const float*)d_in[4];
    const float* q_gamma = (const float*)d_in[5];
    const float* k_gamma = (const float*)d_in[6];
    float* out = (float*)d_out;

    static __half *Wqh_p = nullptr, *Wkvh_p = nullptr, *Woh_p = nullptr;
    static __half *xnh_p = nullptr, *och_p = nullptr, *qprojh_p = nullptr, *kvh_p = nullptr;
    if (!Wqh_p) {   // first call is the non-captured correctness run
        cudaGetSymbolAddress((void**)&Wqh_p, g_Wqh);
        cudaGetSymbolAddress((void**)&Wkvh_p, g_Wkvh);
        cudaGetSymbolAddress((void**)&Woh_p, g_Woh);
        cudaGetSymbolAddress((void**)&xnh_p, g_xnh);
        cudaGetSymbolAddress((void**)&och_p, g_och);
        cudaGetSymbolAddress((void**)&qprojh_p, g_qprojh);
        cudaGetSymbolAddress((void**)&kvh_p, g_kvh);
        cudaFuncSetAttribute(k_attn3, cudaFuncAttributeMaxDynamicSharedMemorySize, ATT3_SMEM);
        cudaFuncSetAttribute(k_gemmh<8, __half>, cudaFuncAttributeMaxDynamicSharedMemorySize, GSM);
        cudaFuncSetAttribute(k_gemmh<8, float>, cudaFuncAttributeMaxDynamicSharedMemorySize, GSM);
    }

    k_pre<<<6656, 256>>>(tokens, norm_w, (const float4*)Wq,
                         (const float4*)Wkv, (const float4*)Wout);
    k_gemmh<8, __half><<<dim3(16, 32), 256, GSM>>>(xnh_p, Wqh_p, Wkvh_p, qprojh_p, kvh_p, 1024);
    k_qknorm<<<3072, 256>>>(q_gamma, k_gamma);
    k_attn3<<<dim3(32, 32), 128, ATT3_SMEM>>>();
    k_combine<<<1024, 256>>>();
    k_gemmh<8, float><<<dim3(8, 32), 256, GSM>>>(och_p, Woh_p, Woh_p, out, out, 512);
}

// round 12
// speedup vs baseline: 1.2349x; 1.0505x over previous
#include <cuda_runtime.h>
#include <cuda_fp16.h>
#include <cstdint>
#include <cstring>
#include <math.h>

#define B_  2
#define N_  2048
#define D_  1024
#define H_  8
#define QH_ 16
#define DH_ 64
#define ROWS (B_*N_)   // 4096

// ---------------- scratch (device globals; no allocs) ----------------
__device__ __half g_xnh[(size_t)ROWS * D_];           // rmsnormed tokens (fp16)
__device__ __half g_qprojh[(size_t)ROWS * 1024];      // x @ Wq (fp16)
__device__ __half g_kvh[(size_t)ROWS * 1024];         // x @ Wkv (fp16)
__device__ __half g_qh[(size_t)B_ * QH_ * N_ * DH_];  // [b][qh][n][dh] fp16
__device__ __half g_kh[(size_t)B_ * H_  * N_ * DH_];  // [b][h][n][dh] fp16
__device__ __half g_vh[(size_t)B_ * H_  * N_ * DH_];  // [b][h][n][dh] fp16
__device__ __half g_oh[(size_t)B_ * QH_ * N_ * DH_];  // per-qhead attn out (fp16)
__device__ __half g_och[(size_t)ROWS * (H_ * DH_)];   // group-summed (fp16)
__device__ __half g_Wqh [(size_t)1024 * 1024];        // fp16 Wq  [k][n]
__device__ __half g_Wkvh[(size_t)1024 * 1024];        // fp16 Wkv [k][n]
__device__ __half g_Woh [(size_t)512 * 1024];         // fp16 Wout[k][n]

// ---------------- helpers ----------------
__device__ __forceinline__ uint32_t smem_u32(const void* p) {
    uint32_t a;
    asm("{ .reg .u64 t; cvta.to.shared.u64 t, %1; cvt.u32.u64 %0, t; }" : "=r"(a) : "l"(p));
    return a;
}
__device__ __forceinline__ uint32_t h2u(__half2 v) {
    uint32_t u;
    memcpy(&u, &v, 4);
    return u;
}
__device__ __forceinline__ void cpa16(uint32_t dst, const void* src) {
    asm volatile("cp.async.ca.shared.global [%0], [%1], 16;" :: "r"(dst), "l"(src));
}
#define CP_COMMIT() asm volatile("cp.async.commit_group;" ::: "memory")
#define CP_WAIT(n)  asm volatile("cp.async.wait_group %0;" :: "n"(n) : "memory")

__device__ __forceinline__ void mmah(float* d, const uint32_t* a, const uint32_t* b) {
    asm volatile("mma.sync.aligned.m16n8k16.row.col.f32.f16.f16.f32 "
                 "{%0,%1,%2,%3}, {%4,%5,%6,%7}, {%8,%9}, {%0,%1,%2,%3};"
                 : "+f"(d[0]), "+f"(d[1]), "+f"(d[2]), "+f"(d[3])
                 : "r"(a[0]), "r"(a[1]), "r"(a[2]), "r"(a[3]),
                   "r"(b[0]), "r"(b[1]));
}
__device__ __forceinline__ void ldsm_x4(uint32_t* r, uint32_t addr) {
    asm volatile("ldmatrix.sync.aligned.m8n8.x4.shared.b16 {%0,%1,%2,%3}, [%4];"
                 : "=r"(r[0]), "=r"(r[1]), "=r"(r[2]), "=r"(r[3]) : "r"(addr));
}
__device__ __forceinline__ void ldsm_x4t(uint32_t* r, uint32_t addr) {
    asm volatile("ldmatrix.sync.aligned.m8n8.x4.trans.shared.b16 {%0,%1,%2,%3}, [%4];"
                 : "=r"(r[0]), "=r"(r[1]), "=r"(r[2]), "=r"(r[3]) : "r"(addr));
}
__device__ __forceinline__ void ldsm_x2t(uint32_t* r, uint32_t addr) {
    asm volatile("ldmatrix.sync.aligned.m8n8.x2.trans.shared.b16 {%0,%1}, [%2];"
                 : "=r"(r[0]), "=r"(r[1]) : "r"(addr));
}
// P = exp(6.25 * tanh(s/50)); tanh via Pade[5/4] (err < 2e-5 for |x|<=1.5).
__device__ __forceinline__ float softcap_exp(float s) {
    float x  = s * 0.02f;
    float x2 = x * x;
    float num = x * fmaf(x2, fmaf(x2, 1.0f, 105.0f), 945.0f);
    float den = fmaf(x2, fmaf(x2, 15.0f, 420.0f), 945.0f);
    return __expf(6.25f * __fdividef(num, den));
}
// epilogue store: fp32 or fp16
__device__ __forceinline__ void st2(float* C, size_t off, float x, float y) {
    *(float2*)(C + off) = make_float2(x, y);
}
__device__ __forceinline__ void st2(__half* C, size_t off, float x, float y) {
    *(__half2*)(C + off) = __floats2half2_rn(x, y);
}

// ---------------- 1) fused RMSNorm->fp16 + weight fp32->fp16 ----------------
__global__ __launch_bounds__(256) void k_pre(const float* __restrict__ x,
                                             const float* __restrict__ w,
                                             const float4* __restrict__ Wq,
                                             const float4* __restrict__ Wkv,
                                             const float4* __restrict__ Wo) {
    if (blockIdx.x < 4096) {
        int row = blockIdx.x;
        const float4* xr = (const float4*)(x + (size_t)row * D_);
        float4 xv = xr[threadIdx.x];
        float ss = xv.x*xv.x + xv.y*xv.y + xv.z*xv.z + xv.w*xv.w;
        #pragma unroll
        for (int o = 16; o; o >>= 1) ss += __shfl_xor_sync(0xffffffffu, ss, o);
        __shared__ float sred[8];
        int wid = threadIdx.x >> 5, lid = threadIdx.x & 31;
        if (lid == 0) sred[wid] = ss;
        __syncthreads();
        if (wid == 0) {
            float v = (lid < 8) ? sred[lid] : 0.0f;
            #pragma unroll
            for (int o = 4; o; o >>= 1) v += __shfl_xor_sync(0xffffffffu, v, o);
            if (lid == 0) sred[0] = v;
        }
        __syncthreads();
        float s = rsqrtf(sred[0] * (1.0f / D_) + 1.192092896e-7f);
        float4 wv = ((const float4*)w)[threadIdx.x];
        __half2* dst = (__half2*)(g_xnh + (size_t)row * D_ + threadIdx.x * 4);
        dst[0] = __floats2half2_rn(xv.x * s * wv.x, xv.y * s * wv.y);
        dst[1] = __floats2half2_rn(xv.z * s * wv.z, xv.w * s * wv.w);
    } else {
        int i = (blockIdx.x - 4096) * 256 + threadIdx.x;   // < 655360
        const float4* src; __half2* dst; int j;
        if (i < 262144)      { src = Wq;  dst = (__half2*)g_Wqh;  j = i; }
        else if (i < 524288) { src = Wkv; dst = (__half2*)g_Wkvh; j = i - 262144; }
        else                 { src = Wo;  dst = (__half2*)g_Woh;  j = i - 524288; }
        float4 v = src[j];
        dst[2 * j]     = __floats2half2_rn(v.x, v.y);
        dst[2 * j + 1] = __floats2half2_rn(v.z, v.w);
    }
}

// ---------------- 2) fp16 mma GEMM, 3-stage cp.async pipeline ----------------
#define HAS 40
#define HBS 136
#define HASZ (128 * HAS)
#define HBSZ (32 * HBS)
#define HSTG (HASZ + HBSZ)          // 9472 halves / stage
#define GSM  (3 * HSTG * 2)         // 56832 bytes dynamic

template <int NX0, typename T>
__global__ __launch_bounds__(256) void k_gemmh(const __half* __restrict__ A,
                                               const __half* __restrict__ W0,
                                               const __half* __restrict__ W1,
                                               T* __restrict__ C0,
                                               T* __restrict__ C1, int K) {
    extern __shared__ __half hs[];
    const int t = threadIdx.x, wid = t >> 5, lane = t & 31;
    const int wm = wid >> 2, wn = wid & 3;
    const int r = lane >> 2, cq = lane & 3;
    const int m0 = blockIdx.y * 128;
    const __half* W; T* C; int n0;
    if ((int)blockIdx.x < NX0) { W = W0; C = C0; n0 = blockIdx.x * 128; }
    else                       { W = W1; C = C1; n0 = (blockIdx.x - NX0) * 128; }
    const uint32_t sb = smem_u32(hs);

    const int qa0 = t, qa1 = t + 256;
    const int ar0 = qa0 >> 2, ac0 = (qa0 & 3) * 8;
    const int ar1 = qa1 >> 2, ac1 = (qa1 & 3) * 8;
    const int br0 = qa0 >> 4, bc0 = (qa0 & 15) * 8;
    const int br1 = qa1 >> 4, bc1 = (qa1 & 15) * 8;

    const int lrow = lane & 7, lt = lane >> 3;
    const int aR = (lt & 1) * 8 + lrow;
    const int aC = (lt >> 1) * 8;
    const int lb = lane & 15, bt = lb >> 3, brw = lb & 7;

    float d[4][4][4];
    #pragma unroll
    for (int i = 0; i < 4; i++)
        #pragma unroll
        for (int j = 0; j < 4; j++)
            #pragma unroll
            for (int v = 0; v < 4; v++) d[i][j][v] = 0.0f;

    const int nc = K >> 5;

    #define LOAD_STAGE(s, c) do { \
        uint32_t ab = sb + (s) * (HSTG * 2); \
        uint32_t bb = ab + HASZ * 2; \
        int k0 = (c) << 5; \
        cpa16(ab + (ar0 * HAS + ac0) * 2, A + (size_t)(m0 + ar0) * K + k0 + ac0); \
        cpa16(ab + (ar1 * HAS + ac1) * 2, A + (size_t)(m0 + ar1) * K + k0 + ac1); \
        cpa16(bb + (br0 * HBS + bc0) * 2, W + (size_t)(k0 + br0) * 1024 + n0 + bc0); \
        cpa16(bb + (br1 * HBS + bc1) * 2, W + (size_t)(k0 + br1) * 1024 + n0 + bc1); \
        CP_COMMIT(); \
    } while (0)

    LOAD_STAGE(0, 0);
    LOAD_STAGE(1, 1);

    for (int c = 0; c < nc; c++) {
        if (c == nc - 1) { CP_WAIT(0); } else { CP_WAIT(1); }
        __syncthreads();
        if (c + 2 < nc) LOAD_STAGE((c + 2) % 3, c + 2);

        uint32_t ab = sb + (c % 3) * (HSTG * 2);
        uint32_t bb = ab + HASZ * 2;
        #pragma unroll
        for (int ks = 0; ks < 2; ks++) {
            uint32_t a[4][4], b[4][2];
            #pragma unroll
            for (int mt = 0; mt < 4; mt++)
                ldsm_x4(a[mt], ab + ((wm * 64 + mt * 16 + aR) * HAS + ks * 16 + aC) * 2);
            #pragma unroll
            for (int nt = 0; nt < 4; nt++)
                ldsm_x2t(b[nt], bb + ((ks * 16 + bt * 8 + brw) * HBS + wn * 32 + nt * 8) * 2);
            #pragma unroll
            for (int mt = 0; mt < 4; mt++)
                #pragma unroll
                for (int nt = 0; nt < 4; nt++) mmah(d[mt][nt], a[mt], b[nt]);
        }
    }

    #pragma unroll
    for (int mt = 0; mt < 4; mt++) {
        int row = m0 + wm * 64 + mt * 16 + r;
        #pragma unroll
        for (int nt = 0; nt < 4; nt++) {
            int col = n0 + wn * 32 + nt * 8 + 2 * cq;
            st2(C, (size_t)row * 1024 + col, d[mt][nt][0], d[mt][nt][1]);
            st2(C, (size_t)(row + 8) * 1024 + col, d[mt][nt][2], d[mt][nt][3]);
        }
    }
    #undef LOAD_STAGE
}

// ---------------- 3) q/k head norm + v copy: uint4 lanes, 8-lane reduce ----------------
__global__ __launch_bounds__(256) void k_qknorm(const float* __restrict__ q_gamma,
                                                const float* __restrict__ k_gamma) {
    int warp = threadIdx.x >> 5, lane = threadIdx.x & 31;
    int sub = lane >> 3, e8 = (lane & 7) * 8;
    int vec = (blockIdx.x * 8 + warp) * 4 + sub;   // < 98304
    if (vec < 65536) {
        int row = vec >> 4, qh = vec & 15;
        uint4 raw = *(const uint4*)(g_qprojh + (size_t)row * 1024 + qh * 64 + e8);
        __half2 hv[4];
        memcpy(hv, &raw, 16);
        float2 f[4];
        float ss = 0.0f;
        #pragma unroll
        for (int j = 0; j < 4; j++) {
            f[j] = __half22float2(hv[j]);
            ss += f[j].x * f[j].x + f[j].y * f[j].y;
        }
        ss += __shfl_xor_sync(0xffffffffu, ss, 1);
        ss += __shfl_xor_sync(0xffffffffu, ss, 2);
        ss += __shfl_xor_sync(0xffffffffu, ss, 4);
        float inv = 1.0f / fmaxf(sqrtf(ss), 1e-12f);
        float4 g0 = *(const float4*)(q_gamma + qh * 64 + e8);
        float4 g1 = *(const float4*)(q_gamma + qh * 64 + e8 + 4);
        __half2 out[4];
        out[0] = __floats2half2_rn(f[0].x * inv * (g0.x + 1.0f) * 8.0f,
                                   f[0].y * inv * (g0.y + 1.0f) * 8.0f);
        out[1] = __floats2half2_rn(f[1].x * inv * (g0.z + 1.0f) * 8.0f,
                                   f[1].y * inv * (g0.w + 1.0f) * 8.0f);
        out[2] = __floats2half2_rn(f[2].x * inv * (g1.x + 1.0f) * 8.0f,
                                   f[2].y * inv * (g1.y + 1.0f) * 8.0f);
        out[3] = __floats2half2_rn(f[3].x * inv * (g1.z + 1.0f) * 8.0f,
                                   f[3].y * inv * (g1.w + 1.0f) * 8.0f);
        int b = row >> 11, n = row & 2047;
        uint4 packed;
        memcpy(&packed, out, 16);
        *(uint4*)(g_qh + ((((size_t)b * QH_ + qh) * N_ + n) * DH_) + e8) = packed;
    } else {
        int v2 = vec - 65536;
        int row = v2 >> 3, h = v2 & 7;
        const __half* base = g_kvh + (size_t)row * 1024 + h * 64 + e8;
        uint4 kraw = *(const uint4*)base;
        uint4 vraw = *(const uint4*)(base + 512);
        __half2 hv[4];
        memcpy(hv, &kraw, 16);
        float2 f[4];
        float ss = 0.0f;
        #pragma unroll
        for (int j = 0; j < 4; j++) {
            f[j] = __half22float2(hv[j]);
            ss += f[j].x * f[j].x + f[j].y * f[j].y;
        }
        ss += __shfl_xor_sync(0xffffffffu, ss, 1);
        ss += __shfl_xor_sync(0xffffffffu, ss, 2);
        ss += __shfl_xor_sync(0xffffffffu, ss, 4);
        float inv = 1.0f / fmaxf(sqrtf(ss), 1e-12f);
        float4 g0 = *(const float4*)(k_gamma + h * 64 + e8);
        float4 g1 = *(const float4*)(k_gamma + h * 64 + e8 + 4);
        __half2 out[4];
        out[0] = __floats2half2_rn(f[0].x * inv * (g0.x + 1.0f) * 8.0f,
                                   f[0].y * inv * (g0.y + 1.0f) * 8.0f);
        out[1] = __floats2half2_rn(f[1].x * inv * (g0.z + 1.0f) * 8.0f,
                                   f[1].y * inv * (g0.w + 1.0f) * 8.0f);
        out[2] = __floats2half2_rn(f[2].x * inv * (g1.x + 1.0f) * 8.0f,
                                   f[2].y * inv * (g1.y + 1.0f) * 8.0f);
        out[3] = __floats2half2_rn(f[3].x * inv * (g1.z + 1.0f) * 8.0f,
                                   f[3].y * inv * (g1.w + 1.0f) * 8.0f);
        int b = row >> 11, n = row & 2047;
        size_t dst = (((size_t)b * H_ + h) * N_ + n) * DH_ + e8;
        uint4 packed;
        memcpy(&packed, out, 16);
        *(uint4*)(g_kh + dst) = packed;
        *(uint4*)(g_vh + dst) = vraw;
    }
}

// ---------------- 4) causal attention: Q-in-reg, paired ldsm.x4 B loads ----------------
// smem halves (stride 72): Q[64] | K[2stg][64] | V[2stg][64]  = 5*4608 halves = 46080 B
#define AQS 72
#define T46 4608
#define OFFK T46
#define OFFV (3 * T46)
#define ATT3_SMEM (5 * T46 * 2)

__global__ __launch_bounds__(128) void k_attn3() {
    extern __shared__ __half sh[];
    const uint32_t sb = smem_u32(sh);

    int bqh = blockIdx.y;                       // b*16 + qh
    int it  = gridDim.x - 1 - blockIdx.x;       // biggest tiles first
    int b = bqh >> 4, qh = bqh & 15, h = qh >> 1;

    const __half* Qg = g_qh + (((size_t)bqh) * N_ + it * 64) * DH_;
    const __half* Kg = g_kh + ((size_t)(b * H_ + h)) * N_ * DH_;
    const __half* Vg = g_vh + ((size_t)(b * H_ + h)) * N_ * DH_;

    const int t = threadIdx.x, wm = t >> 5, lane = t & 31;
    const int r = lane >> 2, cq = lane & 3;
    const int row0 = wm * 16 + r;
    const int lrow = lane & 7, lt = lane >> 3;
    const int aR = (lt & 1) * 8 + lrow, aC = (lt >> 1) * 8;
    const int pn = lt >> 1, pb = (lt & 1) * 8;   // paired-x4: nt offset, bt col/row offset

    // Q tile -> smem
    #pragma unroll
    for (int rep = 0; rep < 4; rep++) {
        int slot = rep * 128 + t;
        int i = slot >> 3, d8 = (slot & 7) * 8;
        *(uint4*)&sh[i * AQS + d8] = *(const uint4*)(Qg + i * 64 + d8);
    }

    #define LOADKV(s, jt_) do { \
        uint32_t kb_ = sb + (OFFK + (s) * T46) * 2; \
        uint32_t vb_ = sb + (OFFV + (s) * T46) * 2; \
        _Pragma("unroll") \
        for (int rep = 0; rep < 4; rep++) { \
            int slot = rep * 128 + t; \
            int j = slot >> 3, d8 = (slot & 7) * 8; \
            cpa16(kb_ + (j * AQS + d8) * 2, Kg + (size_t)((jt_) * 64 + j) * 64 + d8); \
            cpa16(vb_ + (j * AQS + d8) * 2, Vg + (size_t)((jt_) * 64 + j) * 64 + d8); \
        } \
        CP_COMMIT(); \
    } while (0)

    LOADKV(0, 0);
    __syncthreads();   // Q stores visible to ldsm below

    // hoist Q fragments (loop-invariant): 16 regs
    uint32_t qa[4][4];
    #pragma unroll
    for (int ks = 0; ks < 4; ks++)
        ldsm_x4(qa[ks], sb + ((wm * 16 + aR) * AQS + ks * 16 + aC) * 2);

    float o[8][4];
    #pragma unroll
    for (int nt = 0; nt < 8; nt++)
        #pragma unroll
        for (int v = 0; v < 4; v++) o[nt][v] = 0.0f;
    float srow = 0.0f, srow8 = 0.0f;

    for (int jt = 0; jt <= it; jt++) {
        int s = jt & 1;
        CP_WAIT(0);
        __syncthreads();       // stage s visible; prior reads of s^1 done
        if (jt < it) LOADKV(s ^ 1, jt + 1);

        uint32_t kb = sb + (OFFK + s * T46) * 2;
        uint32_t vb = sb + (OFFV + s * T46) * 2;

        // ---- S = Q K^T : paired x4 K loads (2 n-tiles per ldsm) ----
        float dS[8][4];
        #pragma unroll
        for (int nt = 0; nt < 8; nt++)
            #pragma unroll
            for (int v = 0; v < 4; v++) dS[nt][v] = 0.0f;

        #pragma unroll
        for (int ks = 0; ks < 4; ks++) {
            #pragma unroll
            for (int np = 0; np < 4; np++) {   // n-tile pair: nt = 2np, 2np+1
                uint32_t kr[4];
                ldsm_x4(kr, kb + (((2 * np + pn) * 8 + lrow) * AQS + ks * 16 + pb) * 2);
                mmah(dS[2 * np],     qa[ks], kr);
                mmah(dS[2 * np + 1], qa[ks], kr + 2);
            }
        }

        // ---- softcap+exp+mask -> pack P into PV A-fragments ----
        uint32_t ah[4][4];
        if (jt == it) {
            #pragma unroll
            for (int nt = 0; nt < 8; nt++) {
                int colb = nt * 8 + 2 * cq;
                float p0 = (colb     <= row0)     ? softcap_exp(dS[nt][0]) : 0.0f;
                float p1 = (colb + 1 <= row0)     ? softcap_exp(dS[nt][1]) : 0.0f;
                float p2 = (colb     <= row0 + 8) ? softcap_exp(dS[nt][2]) : 0.0f;
                float p3 = (colb + 1 <= row0 + 8) ? softcap_exp(dS[nt][3]) : 0.0f;
                srow  += p0 + p1;
                srow8 += p2 + p3;
                int c = nt >> 1, hi = (nt & 1) * 2;
                ah[c][hi]     = h2u(__floats2half2_rn(p0, p1));
                ah[c][hi + 1] = h2u(__floats2half2_rn(p2, p3));
            }
        } else {
            #pragma unroll
            for (int nt = 0; nt < 8; nt++) {
                float p0 = softcap_exp(dS[nt][0]);
                float p1 = softcap_exp(dS[nt][1]);
                float p2 = softcap_exp(dS[nt][2]);
                float p3 = softcap_exp(dS[nt][3]);
                srow  += p0 + p1;
                srow8 += p2 + p3;
                int c = nt >> 1, hi = (nt & 1) * 2;
                ah[c][hi]     = h2u(__floats2half2_rn(p0, p1));
                ah[c][hi + 1] = h2u(__floats2half2_rn(p2, p3));
            }
        }

        // ---- O += P V : paired x4t V loads (2 dh-tiles per ldsm) ----
        #pragma unroll
        for (int c = 0; c < 4; c++) {
            #pragma unroll
            for (int np = 0; np < 4; np++) {   // dh-tile pair: nt = 2np, 2np+1
                uint32_t vr[4];
                ldsm_x4t(vr, vb + ((c * 16 + pb + lrow) * AQS + (2 * np + pn) * 8) * 2);
                mmah(o[2 * np],     ah[c], vr);
                mmah(o[2 * np + 1], ah[c], vr + 2);
            }
        }
    }

    srow  += __shfl_xor_sync(0xffffffffu, srow, 1);
    srow  += __shfl_xor_sync(0xffffffffu, srow, 2);
    srow8 += __shfl_xor_sync(0xffffffffu, srow8, 1);
    srow8 += __shfl_xor_sync(0xffffffffu, srow8, 2);
    float inv  = 1.0f / srow;
    float inv8 = 1.0f / srow8;

    __half* Og = g_oh + (((size_t)bqh) * N_ + it * 64) * DH_;
    #pragma unroll
    for (int nt = 0; nt < 8; nt++) {
        int colb = nt * 8 + 2 * cq;
        *(__half2*)(Og + (size_t)row0 * 64 + colb) =
            __floats2half2_rn(o[nt][0] * inv, o[nt][1] * inv);
        *(__half2*)(Og + (size_t)(row0 + 8) * 64 + colb) =
            __floats2half2_rn(o[nt][2] * inv8, o[nt][3] * inv8);
    }
    #undef LOADKV
}

// ---------------- 5) group-sum combine (fp16 in/out, 8 halves/thread) ----------------
__global__ __launch_bounds__(256) void k_combine() {
    int s8 = blockIdx.x * 256 + threadIdx.x;   // 8-half slot, < 262144
    int col = (s8 & 63) * 8;
    int row = s8 >> 6;
    int h = col >> 6, dh = col & 63;
    int b = row >> 11, n = row & 2047;
    const __half* o1 = g_oh + ((((size_t)b * QH_ + 2 * h) * N_ + n) * DH_ + dh);
    const __half* o2 = o1 + (size_t)N_ * DH_;
    uint4 araw = *(const uint4*)o1, craw = *(const uint4*)o2;
    __half2 a[4], c[4], y[4];
    memcpy(a, &araw, 16);
    memcpy(c, &craw, 16);
    #pragma unroll
    for (int j = 0; j < 4; j++) {
        float2 fa = __half22float2(a[j]), fc = __half22float2(c[j]);
        y[j] = __floats2half2_rn(fa.x + fc.x, fa.y + fc.y);
    }
    uint4 packed;
    memcpy(&packed, y, 16);
    *(uint4*)(g_och + (size_t)row * 512 + col) = packed;
}

// ---------------- launch ----------------
extern "C" void kernel_launch(void* const* d_in, const int* in_sizes, int n_in,
                              void* d_out, int out_size) {
    const float* tokens  = (const float*)d_in[0];
    const float* norm_w  = (const float*)d_in[1];
    const float* Wq      = (const float*)d_in[2];
    const float* Wkv     = (const float*)d_in[3];
    const float* Wout    = (const float*)d_in[4];
    const float* q_gamma = (const float*)d_in[5];
    const float* k_gamma = (const float*)d_in[6];
    float* out = (float*)d_out;

    static __half *Wqh_p = nullptr, *Wkvh_p = nullptr, *Woh_p = nullptr;
    static __half *xnh_p = nullptr, *och_p = nullptr, *qprojh_p = nullptr, *kvh_p = nullptr;
    if (!Wqh_p) {   // first call is the non-captured correctness run
        cudaGetSymbolAddress((void**)&Wqh_p, g_Wqh);
        cudaGetSymbolAddress((void**)&Wkvh_p, g_Wkvh);
        cudaGetSymbolAddress((void**)&Woh_p, g_Woh);
        cudaGetSymbolAddress((void**)&xnh_p, g_xnh);
        cudaGetSymbolAddress((void**)&och_p, g_och);
        cudaGetSymbolAddress((void**)&qprojh_p, g_qprojh);
        cudaGetSymbolAddress((void**)&kvh_p, g_kvh);
        cudaFuncSetAttribute(k_attn3, cudaFuncAttributeMaxDynamicSharedMemorySize, ATT3_SMEM);
        cudaFuncSetAttribute(k_gemmh<8, __half>, cudaFuncAttributeMaxDynamicSharedMemorySize, GSM);
        cudaFuncSetAttribute(k_gemmh<8, float>, cudaFuncAttributeMaxDynamicSharedMemorySize, GSM);
    }

    k_pre<<<6656, 256>>>(tokens, norm_w, (const float4*)Wq,
                         (const float4*)Wkv, (const float4*)Wout);
    k_gemmh<8, __half><<<dim3(16, 32), 256, GSM>>>(xnh_p, Wqh_p, Wkvh_p, qprojh_p, kvh_p, 1024);
    k_qknorm<<<3072, 256>>>(q_gamma, k_gamma);
    k_attn3<<<dim3(32, 32), 128, ATT3_SMEM>>>();
    k_combine<<<1024, 256>>>();
    k_gemmh<8, float><<<dim3(8, 32), 256, GSM>>>(och_p, Woh_p, Woh_p, out, out, 512);
}